// round 1
// baseline (speedup 1.0000x reference)
#include <cuda_runtime.h>
#include <cstdint>

#define NTOK   131072      // 32 * 4096 tokens
#define DIMS   256
#define NCODE  1024
#define TPB    256
#define TOKB   64          // tokens per block
#define CH     32          // dims per chunk
#define NCH    (DIMS / CH) // 8
#define CT     256         // codes per tile
#define NTILE  (NCODE / CT)// 4

typedef unsigned long long ull;

__device__ float g_esq[NCODE];

__device__ __forceinline__ void ffma2(ull &acc, ull a, ull b) {
    asm("fma.rn.f32x2 %0, %1, %2, %0;" : "+l"(acc) : "l"(a), "l"(b));
}
__device__ __forceinline__ ull packdup(float x) {
    ull r; asm("mov.b64 %0, {%1, %1};" : "=l"(r) : "f"(x)); return r;
}
__device__ __forceinline__ float2 unpk(ull v) {
    float2 r; asm("mov.b64 {%0, %1}, %2;" : "=f"(r.x), "=f"(r.y) : "l"(v)); return r;
}
// order-preserving float -> uint transform (total order incl. negatives)
__device__ __forceinline__ unsigned ordf(float f) {
    unsigned u = __float_as_uint(f);
    return (u & 0x80000000u) ? ~u : (u | 0x80000000u);
}

__global__ void esq_kernel(const float* __restrict__ cb) {
    int k = blockIdx.x * blockDim.x + threadIdx.x;
    if (k >= NCODE) return;
    const float4* r = (const float4*)(cb + (size_t)k * DIMS);
    float s = 0.f;
#pragma unroll 8
    for (int i = 0; i < DIMS / 4; i++) {
        float4 v = r[i];
        s = fmaf(v.x, v.x, s); s = fmaf(v.y, v.y, s);
        s = fmaf(v.z, v.z, s); s = fmaf(v.w, v.w, s);
    }
    g_esq[k] = s;
}

__global__ __launch_bounds__(TPB, 2) void vq_kernel(
    const float* __restrict__ z, const float* __restrict__ cb,
    float* __restrict__ out_zq, float* __restrict__ out_idx)
{
    // dim-major tiles with XOR column swizzle: value for (d, col) stored at
    // column col ^ (4*(d>>2)).  Makes the transpose STS conflict-free while
    // keeping float4 LDS reads conflict-free and 16B-aligned.
    __shared__ __align__(16) float zs[CH][TOKB];
    __shared__ __align__(16) float es[CH][CT];
    __shared__ float zsq_s[TOKB];
    __shared__ float esq_s[CT];
    __shared__ float zpart[4][TOKB];

    const int tid = threadIdx.x;
    const int tx = tid & 31, ty = tid >> 5;
    const size_t tokBase = (size_t)blockIdx.x * TOKB;

    // ---- per-token ||z||^2 (any fp32 order: uniform per-token shift is
    //      argmin-invariant on the fp32 grid at magnitude ~256) ----
    {
        int t = tid & 63, q = tid >> 6;
        const float4* zr = (const float4*)(z + (tokBase + t) * DIMS + q * 64);
        float p = 0.f;
#pragma unroll
        for (int i = 0; i < 16; i++) {
            float4 v = zr[i];
            p = fmaf(v.x, v.x, p); p = fmaf(v.y, v.y, p);
            p = fmaf(v.z, v.z, p); p = fmaf(v.w, v.w, p);
        }
        zpart[q][t] = p;
    }
    __syncthreads();
    if (tid < TOKB)
        zsq_s[tid] = (zpart[0][tid] + zpart[1][tid]) + (zpart[2][tid] + zpart[3][tid]);
    // (consumed only after later __syncthreads barriers)

    ull best[8];
#pragma unroll
    for (int i = 0; i < 8; i++) best[i] = ~0ull;

    for (int tile = 0; tile < NTILE; tile++) {
        const int cbase = tile * CT;

        ull acc[8][4];
#pragma unroll
        for (int i = 0; i < 8; i++)
#pragma unroll
            for (int j = 0; j < 4; j++) acc[i][j] = 0ull;

        for (int ch = 0; ch < NCH; ch++) {
            __syncthreads();
            if (ch == 0) esq_s[tid] = g_esq[cbase + tid];

            // stage z chunk: 64 tokens x 32 dims, transposed + swizzled
#pragma unroll
            for (int i = 0; i < 2; i++) {
                int f = tid + i * TPB;
                int t = f >> 3, dg = f & 7;
                float4 v = *(const float4*)(z + (tokBase + t) * DIMS + ch * CH + dg * 4);
                int s = dg * 4;
                zs[s + 0][t ^ s] = v.x;
                zs[s + 1][t ^ s] = v.y;
                zs[s + 2][t ^ s] = v.z;
                zs[s + 3][t ^ s] = v.w;
            }
            // stage codebook chunk: 256 codes x 32 dims, transposed + swizzled
#pragma unroll
            for (int i = 0; i < 8; i++) {
                int f = tid + i * TPB;
                int c = f >> 3, dg = f & 7;
                float4 v = *(const float4*)(cb + (size_t)(cbase + c) * DIMS + ch * CH + dg * 4);
                int s = dg * 4;
                es[s + 0][c ^ s] = v.x;
                es[s + 1][c ^ s] = v.y;
                es[s + 2][c ^ s] = v.z;
                es[s + 3][c ^ s] = v.w;
            }
            __syncthreads();

#pragma unroll
            for (int dd = 0; dd < CH; dd++) {
                const int s = (dd >> 2) << 2;           // swizzle key, compile-time
                // 8 codes of this thread: {tx*4+j} and {128+tx*4+j}
                ulonglong2 ea = *(const ulonglong2*)&es[dd][(tx * 4) ^ s];
                ulonglong2 eb = *(const ulonglong2*)&es[dd][128 + ((tx * 4) ^ s)];
                // 8 tokens of this thread: ty*8 .. ty*8+7 (broadcast loads)
                const int zb = (ty * 8) ^ (s & 24);
                float4 zlo = *(const float4*)&zs[dd][zb + (s & 4)];        // tokens +0..3
                float4 zhi = *(const float4*)&zs[dd][zb + ((s & 4) ^ 4)];  // tokens +4..7
                float zf0 = zlo.x, zf1 = zlo.y, zf2 = zlo.z, zf3 = zlo.w;
                float zf4 = zhi.x, zf5 = zhi.y, zf6 = zhi.z, zf7 = zhi.w;

                ull zz;
                zz = packdup(zf0); ffma2(acc[0][0], zz, ea.x); ffma2(acc[0][1], zz, ea.y); ffma2(acc[0][2], zz, eb.x); ffma2(acc[0][3], zz, eb.y);
                zz = packdup(zf1); ffma2(acc[1][0], zz, ea.x); ffma2(acc[1][1], zz, ea.y); ffma2(acc[1][2], zz, eb.x); ffma2(acc[1][3], zz, eb.y);
                zz = packdup(zf2); ffma2(acc[2][0], zz, ea.x); ffma2(acc[2][1], zz, ea.y); ffma2(acc[2][2], zz, eb.x); ffma2(acc[2][3], zz, eb.y);
                zz = packdup(zf3); ffma2(acc[3][0], zz, ea.x); ffma2(acc[3][1], zz, ea.y); ffma2(acc[3][2], zz, eb.x); ffma2(acc[3][3], zz, eb.y);
                zz = packdup(zf4); ffma2(acc[4][0], zz, ea.x); ffma2(acc[4][1], zz, ea.y); ffma2(acc[4][2], zz, eb.x); ffma2(acc[4][3], zz, eb.y);
                zz = packdup(zf5); ffma2(acc[5][0], zz, ea.x); ffma2(acc[5][1], zz, ea.y); ffma2(acc[5][2], zz, eb.x); ffma2(acc[5][3], zz, eb.y);
                zz = packdup(zf6); ffma2(acc[6][0], zz, ea.x); ffma2(acc[6][1], zz, ea.y); ffma2(acc[6][2], zz, eb.x); ffma2(acc[6][3], zz, eb.y);
                zz = packdup(zf7); ffma2(acc[7][0], zz, ea.x); ffma2(acc[7][1], zz, ea.y); ffma2(acc[7][2], zz, eb.x); ffma2(acc[7][3], zz, eb.y);
            }
        }

        // epilogue: replicate reference rounding: fl(fl(zsq+esq) - 2*dot)
#pragma unroll
        for (int i = 0; i < 8; i++) {
            float zsq = zsq_s[ty * 8 + i];
#pragma unroll
            for (int j = 0; j < 4; j++) {
                float2 dot = unpk(acc[i][j]);
                int clocal = (j < 2) ? (tx * 4 + j * 2) : (128 + tx * 4 + (j - 2) * 2);
                float s0 = __fadd_rn(zsq, esq_s[clocal]);
                float d0 = __fmaf_rn(-2.f, dot.x, s0);   // fl(2c) exact -> matches fl(s - fl(2c))
                float s1 = __fadd_rn(zsq, esq_s[clocal + 1]);
                float d1 = __fmaf_rn(-2.f, dot.y, s1);
                ull k0 = ((ull)ordf(d0) << 32) | (unsigned)(cbase + clocal);
                ull k1 = ((ull)ordf(d1) << 32) | (unsigned)(cbase + clocal + 1);
                if (k0 < best[i]) best[i] = k0;
                if (k1 < best[i]) best[i] = k1;
            }
        }
    }

    // warp reduce (warp == all tx for fixed ty == owners of the same 8 tokens)
#pragma unroll
    for (int i = 0; i < 8; i++) {
        ull b = best[i];
#pragma unroll
        for (int o = 16; o > 0; o >>= 1) {
            ull ob = __shfl_xor_sync(0xffffffffu, b, o);
            if (ob < b) b = ob;
        }
        unsigned idx = (unsigned)(b & 0xffffffffu);
        size_t tok = tokBase + ty * 8 + i;
        if (out_zq) {
            const float4* src = (const float4*)(cb + (size_t)idx * DIMS);
            float4* dst = (float4*)(out_zq + tok * DIMS);
            dst[tx] = src[tx];
            dst[tx + 32] = src[tx + 32];
        }
        if (out_idx && tx == 0) out_idx[tok] = (float)idx;
    }
}

extern "C" void kernel_launch(void* const* d_in, const int* in_sizes, int n_in,
                              void* d_out, int out_size) {
    const float* z  = (const float*)d_in[0];
    const float* cb = (const float*)d_in[1];
    float* out = (float*)d_out;

    // Output layout: [z_q (NTOK*DIMS floats)] ++ [indices as float (NTOK)].
    // Be defensive about which pieces are present.
    float* out_zq  = nullptr;
    float* out_idx = nullptr;
    const long long ZQ = (long long)NTOK * DIMS;
    if ((long long)out_size >= ZQ + NTOK) {
        out_zq = out;
        out_idx = out + ZQ;
    } else if ((long long)out_size >= ZQ) {
        out_zq = out;
    } else {
        out_idx = out;   // indices-only output
    }

    esq_kernel<<<(NCODE + 255) / 256, 256>>>(cb);
    vq_kernel<<<NTOK / TOKB, TPB>>>(z, cb, out_zq, out_idx);
}

// round 2
// speedup vs baseline: 1.0007x; 1.0007x over previous
#include <cuda_runtime.h>
#include <cstdint>

#define NTOK   131072      // 32 * 4096 tokens
#define DIMS   256
#define NCODE  1024
#define TPB    256
#define TOKB   64          // tokens per block
#define CH     32          // dims per chunk
#define NCH    (DIMS / CH) // 8
#define CT     256         // codes per tile
#define NTILE  (NCODE / CT)// 4

typedef unsigned long long ull;

__device__ float g_esq[NCODE];

__device__ __forceinline__ void ffma2(ull &acc, ull a, ull b) {
    asm("fma.rn.f32x2 %0, %1, %2, %0;" : "+l"(acc) : "l"(a), "l"(b));
}
__device__ __forceinline__ ull packdup(float x) {
    ull r; asm("mov.b64 %0, {%1, %1};" : "=l"(r) : "f"(x)); return r;
}
__device__ __forceinline__ float2 unpk(ull v) {
    float2 r; asm("mov.b64 {%0, %1}, %2;" : "=f"(r.x), "=f"(r.y) : "l"(v)); return r;
}
// order-preserving float -> uint transform (total order incl. negatives)
__device__ __forceinline__ unsigned ordf(float f) {
    unsigned u = __float_as_uint(f);
    return (u & 0x80000000u) ? ~u : (u | 0x80000000u);
}

__global__ void esq_kernel(const float* __restrict__ cb) {
    int k = blockIdx.x * blockDim.x + threadIdx.x;
    if (k >= NCODE) return;
    const float4* r = (const float4*)(cb + (size_t)k * DIMS);
    float s = 0.f;
#pragma unroll 8
    for (int i = 0; i < DIMS / 4; i++) {
        float4 v = r[i];
        s = fmaf(v.x, v.x, s); s = fmaf(v.y, v.y, s);
        s = fmaf(v.z, v.z, s); s = fmaf(v.w, v.w, s);
    }
    g_esq[k] = s;
}

__global__ __launch_bounds__(TPB, 2) void vq_kernel(
    const float* __restrict__ z, const float* __restrict__ cb,
    float* __restrict__ out_zq, float* __restrict__ out_idx)
{
    // dim-major tiles with XOR column swizzle: value for (d, col) stored at
    // column col ^ (4*(d>>2)).  Makes the transpose STS conflict-free while
    // keeping float4 LDS reads conflict-free and 16B-aligned.
    __shared__ __align__(16) float zs[CH][TOKB];
    __shared__ __align__(16) float es[CH][CT];
    __shared__ float zsq_s[TOKB];
    __shared__ float esq_s[CT];
    __shared__ float zpart[4][TOKB];

    const int tid = threadIdx.x;
    const int tx = tid & 31, ty = tid >> 5;
    const size_t tokBase = (size_t)blockIdx.x * TOKB;

    // ---- per-token ||z||^2 (any fp32 order: uniform per-token shift is
    //      argmin-invariant on the fp32 grid at magnitude ~256) ----
    {
        int t = tid & 63, q = tid >> 6;
        const float4* zr = (const float4*)(z + (tokBase + t) * DIMS + q * 64);
        float p = 0.f;
#pragma unroll
        for (int i = 0; i < 16; i++) {
            float4 v = zr[i];
            p = fmaf(v.x, v.x, p); p = fmaf(v.y, v.y, p);
            p = fmaf(v.z, v.z, p); p = fmaf(v.w, v.w, p);
        }
        zpart[q][t] = p;
    }
    __syncthreads();
    if (tid < TOKB)
        zsq_s[tid] = (zpart[0][tid] + zpart[1][tid]) + (zpart[2][tid] + zpart[3][tid]);
    // (consumed only after later __syncthreads barriers)

    ull best[8];
#pragma unroll
    for (int i = 0; i < 8; i++) best[i] = ~0ull;

    for (int tile = 0; tile < NTILE; tile++) {
        const int cbase = tile * CT;

        ull acc[8][4];
#pragma unroll
        for (int i = 0; i < 8; i++)
#pragma unroll
            for (int j = 0; j < 4; j++) acc[i][j] = 0ull;

        for (int ch = 0; ch < NCH; ch++) {
            __syncthreads();
            if (ch == 0) esq_s[tid] = g_esq[cbase + tid];

            // stage z chunk: 64 tokens x 32 dims, transposed + swizzled
#pragma unroll
            for (int i = 0; i < 2; i++) {
                int f = tid + i * TPB;
                int t = f >> 3, dg = f & 7;
                float4 v = *(const float4*)(z + (tokBase + t) * DIMS + ch * CH + dg * 4);
                int s = dg * 4;
                zs[s + 0][t ^ s] = v.x;
                zs[s + 1][t ^ s] = v.y;
                zs[s + 2][t ^ s] = v.z;
                zs[s + 3][t ^ s] = v.w;
            }
            // stage codebook chunk: 256 codes x 32 dims, transposed + swizzled
#pragma unroll
            for (int i = 0; i < 8; i++) {
                int f = tid + i * TPB;
                int c = f >> 3, dg = f & 7;
                float4 v = *(const float4*)(cb + (size_t)(cbase + c) * DIMS + ch * CH + dg * 4);
                int s = dg * 4;
                es[s + 0][c ^ s] = v.x;
                es[s + 1][c ^ s] = v.y;
                es[s + 2][c ^ s] = v.z;
                es[s + 3][c ^ s] = v.w;
            }
            __syncthreads();

#pragma unroll
            for (int dd = 0; dd < CH; dd++) {
                const int s = (dd >> 2) << 2;           // swizzle key, compile-time
                // 8 codes of this thread: {tx*4+j} and {128+tx*4+j}
                ulonglong2 ea = *(const ulonglong2*)&es[dd][(tx * 4) ^ s];
                ulonglong2 eb = *(const ulonglong2*)&es[dd][128 + ((tx * 4) ^ s)];
                // 8 tokens of this thread: ty*8 .. ty*8+7 (broadcast loads)
                const int zb = (ty * 8) ^ (s & 24);
                float4 zlo = *(const float4*)&zs[dd][zb + (s & 4)];        // tokens +0..3
                float4 zhi = *(const float4*)&zs[dd][zb + ((s & 4) ^ 4)];  // tokens +4..7
                float zf0 = zlo.x, zf1 = zlo.y, zf2 = zlo.z, zf3 = zlo.w;
                float zf4 = zhi.x, zf5 = zhi.y, zf6 = zhi.z, zf7 = zhi.w;

                ull zz;
                zz = packdup(zf0); ffma2(acc[0][0], zz, ea.x); ffma2(acc[0][1], zz, ea.y); ffma2(acc[0][2], zz, eb.x); ffma2(acc[0][3], zz, eb.y);
                zz = packdup(zf1); ffma2(acc[1][0], zz, ea.x); ffma2(acc[1][1], zz, ea.y); ffma2(acc[1][2], zz, eb.x); ffma2(acc[1][3], zz, eb.y);
                zz = packdup(zf2); ffma2(acc[2][0], zz, ea.x); ffma2(acc[2][1], zz, ea.y); ffma2(acc[2][2], zz, eb.x); ffma2(acc[2][3], zz, eb.y);
                zz = packdup(zf3); ffma2(acc[3][0], zz, ea.x); ffma2(acc[3][1], zz, ea.y); ffma2(acc[3][2], zz, eb.x); ffma2(acc[3][3], zz, eb.y);
                zz = packdup(zf4); ffma2(acc[4][0], zz, ea.x); ffma2(acc[4][1], zz, ea.y); ffma2(acc[4][2], zz, eb.x); ffma2(acc[4][3], zz, eb.y);
                zz = packdup(zf5); ffma2(acc[5][0], zz, ea.x); ffma2(acc[5][1], zz, ea.y); ffma2(acc[5][2], zz, eb.x); ffma2(acc[5][3], zz, eb.y);
                zz = packdup(zf6); ffma2(acc[6][0], zz, ea.x); ffma2(acc[6][1], zz, ea.y); ffma2(acc[6][2], zz, eb.x); ffma2(acc[6][3], zz, eb.y);
                zz = packdup(zf7); ffma2(acc[7][0], zz, ea.x); ffma2(acc[7][1], zz, ea.y); ffma2(acc[7][2], zz, eb.x); ffma2(acc[7][3], zz, eb.y);
            }
        }

        // epilogue: replicate reference rounding: fl(fl(zsq+esq) - 2*dot)
#pragma unroll
        for (int i = 0; i < 8; i++) {
            float zsq = zsq_s[ty * 8 + i];
#pragma unroll
            for (int j = 0; j < 4; j++) {
                float2 dot = unpk(acc[i][j]);
                int clocal = (j < 2) ? (tx * 4 + j * 2) : (128 + tx * 4 + (j - 2) * 2);
                float s0 = __fadd_rn(zsq, esq_s[clocal]);
                float d0 = __fmaf_rn(-2.f, dot.x, s0);   // fl(2c) exact -> matches fl(s - fl(2c))
                float s1 = __fadd_rn(zsq, esq_s[clocal + 1]);
                float d1 = __fmaf_rn(-2.f, dot.y, s1);
                ull k0 = ((ull)ordf(d0) << 32) | (unsigned)(cbase + clocal);
                ull k1 = ((ull)ordf(d1) << 32) | (unsigned)(cbase + clocal + 1);
                if (k0 < best[i]) best[i] = k0;
                if (k1 < best[i]) best[i] = k1;
            }
        }
    }

    // warp reduce (warp == all tx for fixed ty == owners of the same 8 tokens)
#pragma unroll
    for (int i = 0; i < 8; i++) {
        ull b = best[i];
#pragma unroll
        for (int o = 16; o > 0; o >>= 1) {
            ull ob = __shfl_xor_sync(0xffffffffu, b, o);
            if (ob < b) b = ob;
        }
        unsigned idx = (unsigned)(b & 0xffffffffu);
        size_t tok = tokBase + ty * 8 + i;
        if (out_zq) {
            const float4* src = (const float4*)(cb + (size_t)idx * DIMS);
            float4* dst = (float4*)(out_zq + tok * DIMS);
            dst[tx] = src[tx];
            dst[tx + 32] = src[tx + 32];
        }
        if (out_idx && tx == 0) out_idx[tok] = (float)idx;
    }
}

extern "C" void kernel_launch(void* const* d_in, const int* in_sizes, int n_in,
                              void* d_out, int out_size) {
    const float* z  = (const float*)d_in[0];
    const float* cb = (const float*)d_in[1];
    float* out = (float*)d_out;

    // Output layout: [z_q (NTOK*DIMS floats)] ++ [indices as float (NTOK)].
    // Be defensive about which pieces are present.
    float* out_zq  = nullptr;
    float* out_idx = nullptr;
    const long long ZQ = (long long)NTOK * DIMS;
    if ((long long)out_size >= ZQ + NTOK) {
        out_zq = out;
        out_idx = out + ZQ;
    } else if ((long long)out_size >= ZQ) {
        out_zq = out;
    } else {
        out_idx = out;   // indices-only output
    }

    esq_kernel<<<(NCODE + 255) / 256, 256>>>(cb);
    vq_kernel<<<NTOK / TOKB, TPB>>>(z, cb, out_zq, out_idx);
}

// round 4
// speedup vs baseline: 1.7899x; 1.7886x over previous
#include <cuda_runtime.h>
#include <cuda_bf16.h>
#include <cstdint>

#define NTOK   131072
#define DIMS   256
#define NCODE  1024
#define TOKB   128
#define NCH    64                 // codes per B chunk
#define NCHUNK (NCODE / NCH)      // 16
#define MARGIN 5e-4f

// smem layout (bytes)
#define SA    0                   // A: 128 rows x 512 bf16 (hi||lo), stride 1024B, swizzled
#define SB    131072              // B: 2 x (64 rows x 256 bf16, stride 512B, swizzled)
#define SBSZ  32768
#define SESQ  196608              // 1024 f32
#define SR1V  200704
#define SR1I  202752
#define SR2V  204800
#define SR2I  206848
#define SR3V  208896
#define SIDX  210944
#define SMEM_BYTES 211456

typedef unsigned long long ull;
typedef unsigned int u32;

__device__ float g_esq[NCODE];
__device__ int   g_npair, g_nfull;
__device__ ull   g_pair[NTOK];
__device__ u32   g_full[NTOK];
__device__ __align__(16) __nv_bfloat16 g_Bh[(size_t)NCODE * DIMS];

__device__ __forceinline__ u32 s2u(const void* p) {
    u32 a; asm("{ .reg .u64 t; cvta.to.shared.u64 t, %1; cvt.u32.u64 %0, t; }" : "=r"(a) : "l"(p)); return a;
}
__device__ __forceinline__ void cpa16(u32 dst, const void* src) {
    asm volatile("cp.async.cg.shared.global [%0], [%1], 16;" :: "r"(dst), "l"(src));
}
#define CPA_COMMIT() asm volatile("cp.async.commit_group;" ::: "memory")
#define CPA_WAIT1()  asm volatile("cp.async.wait_group 1;"  ::: "memory")
#define CPA_WAIT0()  asm volatile("cp.async.wait_group 0;"  ::: "memory")

__device__ __forceinline__ void ldsm4(u32* r, u32 addr) {
    asm volatile("ldmatrix.sync.aligned.m8n8.x4.shared.b16 {%0,%1,%2,%3}, [%4];"
                 : "=r"(r[0]), "=r"(r[1]), "=r"(r[2]), "=r"(r[3]) : "r"(addr));
}
__device__ __forceinline__ void mma16816(float* c, const u32* a, const u32* b) {
    asm volatile("mma.sync.aligned.m16n8k16.row.col.f32.bf16.bf16.f32 "
                 "{%0,%1,%2,%3}, {%4,%5,%6,%7}, {%8,%9}, {%0,%1,%2,%3};"
                 : "+f"(c[0]), "+f"(c[1]), "+f"(c[2]), "+f"(c[3])
                 : "r"(a[0]), "r"(a[1]), "r"(a[2]), "r"(a[3]), "r"(b[0]), "r"(b[1]));
}
__device__ __forceinline__ u32 packbf(float lo, float hi) {   // low 16 <- lo
    u32 r; asm("cvt.rn.bf16x2.f32 %0, %1, %2;" : "=r"(r) : "f"(hi), "f"(lo)); return r;
}
__device__ __forceinline__ u32 ordf(float f) {
    u32 u = __float_as_uint(f);
    return (u & 0x80000000u) ? ~u : (u | 0x80000000u);
}
// merge sorted top-3 (v1,i1,v2,i2,v3) with another sorted top-3
__device__ __forceinline__ void merge3(float &v1, u32 &i1, float &v2, u32 &i2, float &v3,
                                       float o1, u32 oi1, float o2, u32 oi2, float o3) {
    if (o1 < v1) {
        if (v1 <= o2) { v3 = fminf(v2, o2); v2 = v1; i2 = i1; }
        else          { v3 = fminf(v1, o3); v2 = o2; i2 = oi2; }
        v1 = o1; i1 = oi1;
    } else {
        if (o1 < v2) { v3 = fminf(v2, o2); v2 = o1; i2 = oi1; }
        else         { v3 = fminf(v3, o1); }
    }
}

// ---------------- prep ----------------
__global__ void esq_kernel(const float* __restrict__ cb) {
    if (blockIdx.x == 0 && threadIdx.x == 0) { g_npair = 0; g_nfull = 0; }
    int k = blockIdx.x * blockDim.x + threadIdx.x;
    if (k >= NCODE) return;
    const float4* r = (const float4*)(cb + (size_t)k * DIMS);
    float s = 0.f;
#pragma unroll 8
    for (int i = 0; i < DIMS / 4; i++) {
        float4 v = r[i];
        s = fmaf(v.x, v.x, s); s = fmaf(v.y, v.y, s);
        s = fmaf(v.z, v.z, s); s = fmaf(v.w, v.w, s);
    }
    g_esq[k] = s;
}
__global__ void bprep_kernel(const float* __restrict__ cb) {
    int i = blockIdx.x * blockDim.x + threadIdx.x;       // one per element
    g_Bh[i] = __float2bfloat16(cb[i]);
}

// ---------------- main: HMMA GEMM + top-3 argmin ----------------
__global__ __launch_bounds__(256, 1) void vq_kernel(
    const float* __restrict__ z, const float* __restrict__ cb,
    float* __restrict__ out_zq, float* __restrict__ out_idx)
{
    extern __shared__ __align__(16) unsigned char smem[];
    const u32 smb = s2u(smem);
    float* esq_s = (float*)(smem + SESQ);
    float* r1v = (float*)(smem + SR1V); u32* r1i = (u32*)(smem + SR1I);
    float* r2v = (float*)(smem + SR2V); u32* r2i = (u32*)(smem + SR2I);
    float* r3v = (float*)(smem + SR3V); u32* idx_s = (u32*)(smem + SIDX);

    const int tid = threadIdx.x, lane = tid & 31, wid = tid >> 5;
    const int wm = wid & 1, wn = wid >> 1;
    const size_t tokBase = (size_t)blockIdx.x * TOKB;

    // kick B chunk 0
    {
        const int ch = 0;
#pragma unroll
        for (int i = 0; i < 8; i++) {
            int flat = tid + i * 256, row = flat >> 5, g = flat & 31;
            u32 dst = smb + SB + (u32)row * 512 + (u32)((g ^ (row & 7)) << 4);
            cpa16(dst, g_Bh + ((size_t)(ch * NCH + row) * DIMS + g * 8));
        }
        CPA_COMMIT();
    }
    // A: convert z -> bf16 hi/lo into smem (swizzled), while B0 is in flight
#pragma unroll
    for (int i = 0; i < 16; i++) {
        int flat = tid + i * 256, row = flat >> 5, g = flat & 31;
        const float4* zp = (const float4*)(z + (tokBase + row) * DIMS + g * 8);
        float4 a = zp[0], b = zp[1];
        float hax = __bfloat162float(__float2bfloat16(a.x)), hay = __bfloat162float(__float2bfloat16(a.y));
        float haz = __bfloat162float(__float2bfloat16(a.z)), haw = __bfloat162float(__float2bfloat16(a.w));
        float hbx = __bfloat162float(__float2bfloat16(b.x)), hby = __bfloat162float(__float2bfloat16(b.y));
        float hbz = __bfloat162float(__float2bfloat16(b.z)), hbw = __bfloat162float(__float2bfloat16(b.w));
        u32 h0 = packbf(a.x, a.y), h1 = packbf(a.z, a.w), h2 = packbf(b.x, b.y), h3 = packbf(b.z, b.w);
        u32 l0 = packbf(a.x - hax, a.y - hay), l1 = packbf(a.z - haz, a.w - haw);
        u32 l2 = packbf(b.x - hbx, b.y - hby), l3 = packbf(b.z - hbz, b.w - hbw);
        u32 ah = smb + SA + (u32)row * 1024 + (u32)((g ^ (row & 7)) << 4);
        asm volatile("st.shared.v4.b32 [%0], {%1,%2,%3,%4};" :: "r"(ah), "r"(h0), "r"(h1), "r"(h2), "r"(h3));
        asm volatile("st.shared.v4.b32 [%0], {%1,%2,%3,%4};" :: "r"(ah + 512), "r"(l0), "r"(l1), "r"(l2), "r"(l3));
    }
#pragma unroll
    for (int i = 0; i < 4; i++) esq_s[tid + i * 256] = g_esq[tid + i * 256];

    // per-warp ldmatrix bases
    const int t8 = lane >> 3;
    u32 aBase[4]; int aSw[4];
#pragma unroll
    for (int mt = 0; mt < 4; mt++) {
        int ar = wm * 64 + mt * 16 + (t8 & 1) * 8 + (lane & 7);
        aSw[mt] = ar & 7; aBase[mt] = smb + SA + (u32)ar * 1024;
    }
    const int akt = (lane >> 4) & 1;            // k-high-8 select for A
    const int br = wn * 16 + (t8 >> 1) * 8 + (lane & 7);
    const int bSw = br & 7, bkt = t8 & 1;
    const u32 bRowOff = (u32)br * 512;

    // top-3 per row-slot
    float b1v[8], b2v[8], b3v[8]; u32 b1i[8], b2i[8];
#pragma unroll
    for (int s = 0; s < 8; s++) { b1v[s] = b2v[s] = b3v[s] = 3.4e38f; b1i[s] = b2i[s] = 0; }

    for (int ch = 0; ch < NCHUNK; ch++) {
        if (ch < NCHUNK - 1) {
            const int nc = ch + 1;
#pragma unroll
            for (int i = 0; i < 8; i++) {
                int flat = tid + i * 256, row = flat >> 5, g = flat & 31;
                u32 dst = smb + SB + (u32)((nc & 1) ? SBSZ : 0) + (u32)row * 512 + (u32)((g ^ (row & 7)) << 4);
                cpa16(dst, g_Bh + ((size_t)(nc * NCH + row) * DIMS + g * 8));
            }
            CPA_COMMIT();
            CPA_WAIT1();
        } else {
            CPA_WAIT0();
        }
        __syncthreads();

        const u32 bb = smb + SB + (u32)((ch & 1) ? SBSZ : 0) + bRowOff;
        float acc[4][2][4];
#pragma unroll
        for (int mt = 0; mt < 4; mt++)
#pragma unroll
            for (int nt = 0; nt < 2; nt++)
#pragma unroll
                for (int i = 0; i < 4; i++) acc[mt][nt][i] = 0.f;

#pragma unroll 4
        for (int ks = 0; ks < 16; ks++) {
            u32 bF[4], aFh[4][4], aFl[4][4];
            ldsm4(bF, bb + (u32)(((ks * 2 + bkt) ^ bSw) << 4));
#pragma unroll
            for (int mt = 0; mt < 4; mt++)
                ldsm4(aFh[mt], aBase[mt] + (u32)(((ks * 2 + akt) ^ aSw[mt]) << 4));
#pragma unroll
            for (int mt = 0; mt < 4; mt++)
                ldsm4(aFl[mt], aBase[mt] + (u32)(((32 + ks * 2 + akt) ^ aSw[mt]) << 4));
#pragma unroll
            for (int mt = 0; mt < 4; mt++) {
                mma16816(acc[mt][0], aFh[mt], bF);
                mma16816(acc[mt][1], aFh[mt], bF + 2);
            }
#pragma unroll
            for (int mt = 0; mt < 4; mt++) {
                mma16816(acc[mt][0], aFl[mt], bF);
                mma16816(acc[mt][1], aFl[mt], bF + 2);
            }
        }

        // epilogue: m = esq - 2*dot, top-3 update
#pragma unroll
        for (int mt = 0; mt < 4; mt++)
#pragma unroll
            for (int nt = 0; nt < 2; nt++)
#pragma unroll
                for (int i = 0; i < 4; i++) {
                    int c = ch * NCH + wn * 16 + nt * 8 + 2 * (lane & 3) + (i & 1);
                    float m = fmaf(-2.f, acc[mt][nt][i], esq_s[c]);
                    int s = mt * 2 + (i >> 1);
                    if (m < b1v[s]) { b3v[s] = b2v[s]; b2v[s] = b1v[s]; b2i[s] = b1i[s]; b1v[s] = m; b1i[s] = (u32)c; }
                    else if (m < b2v[s]) { b3v[s] = b2v[s]; b2v[s] = m; b2i[s] = (u32)c; }
                    else if (m < b3v[s]) b3v[s] = m;
                }
        __syncthreads();
    }

    // quad-lane merge (lanes sharing lane>>2 hold same token rows)
#pragma unroll
    for (int s = 0; s < 8; s++) {
#pragma unroll
        for (int x = 1; x <= 2; x <<= 1) {
            float o1 = __shfl_xor_sync(~0u, b1v[s], x); u32 oi1 = __shfl_xor_sync(~0u, b1i[s], x);
            float o2 = __shfl_xor_sync(~0u, b2v[s], x); u32 oi2 = __shfl_xor_sync(~0u, b2i[s], x);
            float o3 = __shfl_xor_sync(~0u, b3v[s], x);
            merge3(b1v[s], b1i[s], b2v[s], b2i[s], b3v[s], o1, oi1, o2, oi2, o3);
        }
    }
    if ((lane & 3) == 0) {
#pragma unroll
        for (int s = 0; s < 8; s++) {
            int grow = wm * 64 + (s >> 1) * 16 + (lane >> 2) + (s & 1) * 8;
            r1v[wn * 128 + grow] = b1v[s]; r1i[wn * 128 + grow] = b1i[s];
            r2v[wn * 128 + grow] = b2v[s]; r2i[wn * 128 + grow] = b2i[s];
            r3v[wn * 128 + grow] = b3v[s];
        }
    }
    __syncthreads();

    if (tid < 128) {
        float v1 = r1v[tid]; u32 i1 = r1i[tid]; float v2 = r2v[tid]; u32 i2 = r2i[tid]; float v3 = r3v[tid];
#pragma unroll
        for (int w = 1; w < 4; w++)
            merge3(v1, i1, v2, i2, v3, r1v[w * 128 + tid], r1i[w * 128 + tid],
                   r2v[w * 128 + tid], r2i[w * 128 + tid], r3v[w * 128 + tid]);
        const size_t tok = tokBase + tid;
        idx_s[tid] = i1;
        if (out_idx) out_idx[tok] = (float)i1;
        if (v2 - v1 < MARGIN) {
            if (v3 - v1 >= MARGIN) {
                int p = atomicAdd(&g_npair, 1);
                g_pair[p] = (ull)tok | ((ull)i1 << 20) | ((ull)i2 << 32);
            } else {
                int p = atomicAdd(&g_nfull, 1);
                g_full[p] = (u32)tok;
            }
        }
    }
    __syncthreads();

    if (out_zq) {
#pragma unroll
        for (int i = 0; i < 32; i++) {
            int flat = tid + i * 256, t = flat >> 6, v = flat & 63;
            ((float4*)(out_zq + (tokBase + t) * DIMS))[v] =
                ((const float4*)(cb + (size_t)idx_s[t] * DIMS))[v];
        }
    }
}

// ---------------- exact pair rescore (2 candidates) ----------------
__global__ __launch_bounds__(256) void pair_kernel(
    const float* __restrict__ z, const float* __restrict__ cb,
    float* __restrict__ out_zq, float* __restrict__ out_idx)
{
    const int lane = threadIdx.x & 31;
    const int gw = (blockIdx.x * blockDim.x + threadIdx.x) >> 5;
    const int nw = (gridDim.x * blockDim.x) >> 5;
    const int n = g_npair;
    for (int i = gw; i < n; i += nw) {
        ull p = g_pair[i];
        u32 tok = (u32)(p & 0xFFFFFu), c1 = (u32)((p >> 20) & 0x3FFu), c2 = (u32)((p >> 32) & 0x3FFu);
        const float4* zp = (const float4*)(z + (size_t)tok * DIMS + lane * 8);
        const float4* e1 = (const float4*)(cb + (size_t)c1 * DIMS + lane * 8);
        const float4* e2 = (const float4*)(cb + (size_t)c2 * DIMS + lane * 8);
        float4 za = zp[0], zb = zp[1], a1 = e1[0], b1 = e1[1], a2 = e2[0], b2 = e2[1];
        float zsq = za.x * za.x, d1 = za.x * a1.x, d2 = za.x * a2.x;
        zsq = fmaf(za.y, za.y, zsq); d1 = fmaf(za.y, a1.y, d1); d2 = fmaf(za.y, a2.y, d2);
        zsq = fmaf(za.z, za.z, zsq); d1 = fmaf(za.z, a1.z, d1); d2 = fmaf(za.z, a2.z, d2);
        zsq = fmaf(za.w, za.w, zsq); d1 = fmaf(za.w, a1.w, d1); d2 = fmaf(za.w, a2.w, d2);
        zsq = fmaf(zb.x, zb.x, zsq); d1 = fmaf(zb.x, b1.x, d1); d2 = fmaf(zb.x, b2.x, d2);
        zsq = fmaf(zb.y, zb.y, zsq); d1 = fmaf(zb.y, b1.y, d1); d2 = fmaf(zb.y, b2.y, d2);
        zsq = fmaf(zb.z, zb.z, zsq); d1 = fmaf(zb.z, b1.z, d1); d2 = fmaf(zb.z, b2.z, d2);
        zsq = fmaf(zb.w, zb.w, zsq); d1 = fmaf(zb.w, b1.w, d1); d2 = fmaf(zb.w, b2.w, d2);
#pragma unroll
        for (int o = 16; o > 0; o >>= 1) {
            zsq += __shfl_xor_sync(~0u, zsq, o);
            d1 += __shfl_xor_sync(~0u, d1, o);
            d2 += __shfl_xor_sync(~0u, d2, o);
        }
        u32 widx;
        {
            float dd1 = __fmaf_rn(-2.f, d1, __fadd_rn(zsq, g_esq[c1]));
            float dd2 = __fmaf_rn(-2.f, d2, __fadd_rn(zsq, g_esq[c2]));
            ull k1 = ((ull)ordf(dd1) << 32) | c1, k2 = ((ull)ordf(dd2) << 32) | c2;
            widx = (u32)((k1 < k2 ? k1 : k2) & 0xffffffffu);
        }
        if (out_idx && lane == 0) out_idx[tok] = (float)widx;
        if (out_zq) {
            const float4* src = (const float4*)(cb + (size_t)widx * DIMS);
            float4* dst = (float4*)(out_zq + (size_t)tok * DIMS);
            dst[lane] = src[lane];
            dst[lane + 32] = src[lane + 32];
        }
    }
}

// ---------------- exact full rescore (rare multi-candidate tokens) ----------------
__global__ __launch_bounds__(256) void full_kernel(
    const float* __restrict__ z, const float* __restrict__ cb,
    float* __restrict__ out_zq, float* __restrict__ out_idx)
{
    __shared__ float zrow[DIMS];
    __shared__ float zsq_sh;
    __shared__ ull wb[8];
    __shared__ u32 ridx;
    const int t = threadIdx.x, lane = t & 31, w = t >> 5;
    const int n = g_nfull;
    for (int it = blockIdx.x; it < n; it += gridDim.x) {
        const size_t tok = g_full[it];
        zrow[t] = z[tok * DIMS + t];
        __syncthreads();
        if (w == 0) {
            const float* zp = &zrow[lane * 8];
            float p = zp[0] * zp[0];
#pragma unroll
            for (int i = 1; i < 8; i++) p = fmaf(zp[i], zp[i], p);
#pragma unroll
            for (int o = 16; o > 0; o >>= 1) p += __shfl_xor_sync(~0u, p, o);
            if (lane == 0) zsq_sh = p;
        }
        __syncthreads();
        const float zsq = zsq_sh;
        ull best = ~0ull;
        for (int j = 0; j < 128; j++) {
            const int c = w * 128 + j;
            const float4* e4 = (const float4*)(cb + (size_t)c * DIMS + lane * 8);
            float4 a = e4[0], b = e4[1];
            const float* zp = &zrow[lane * 8];
            float p = zp[0] * a.x;
            p = fmaf(zp[1], a.y, p); p = fmaf(zp[2], a.z, p); p = fmaf(zp[3], a.w, p);
            p = fmaf(zp[4], b.x, p); p = fmaf(zp[5], b.y, p); p = fmaf(zp[6], b.z, p);
            p = fmaf(zp[7], b.w, p);
#pragma unroll
            for (int o = 16; o > 0; o >>= 1) p += __shfl_xor_sync(~0u, p, o);
            if (lane == 0) {
                float d = __fmaf_rn(-2.f, p, __fadd_rn(zsq, g_esq[c]));
                ull pk = ((ull)ordf(d) << 32) | (u32)c;
                if (pk < best) best = pk;
            }
        }
        if (lane == 0) wb[w] = best;
        __syncthreads();
        if (t == 0) {
            ull b = wb[0];
#pragma unroll
            for (int i = 1; i < 8; i++) if (wb[i] < b) b = wb[i];
            ridx = (u32)(b & 0xffffffffu);
            if (out_idx) out_idx[tok] = (float)ridx;
        }
        __syncthreads();
        if (out_zq && t < 64)
            ((float4*)(out_zq + tok * DIMS))[t] = ((const float4*)(cb + (size_t)ridx * DIMS))[t];
        __syncthreads();
    }
}

extern "C" void kernel_launch(void* const* d_in, const int* in_sizes, int n_in,
                              void* d_out, int out_size) {
    const float* z  = (const float*)d_in[0];
    const float* cb = (const float*)d_in[1];
    float* out = (float*)d_out;
    float* out_zq = nullptr;
    float* out_idx = nullptr;
    const long long ZQ = (long long)NTOK * DIMS;
    if ((long long)out_size >= ZQ + NTOK) { out_zq = out; out_idx = out + ZQ; }
    else if ((long long)out_size >= ZQ)   { out_zq = out; }
    else                                  { out_idx = out; }

    cudaFuncSetAttribute(vq_kernel, cudaFuncAttributeMaxDynamicSharedMemorySize, SMEM_BYTES);

    esq_kernel<<<4, 256>>>(cb);
    bprep_kernel<<<NCODE, 256>>>(cb);
    vq_kernel<<<NTOK / TOKB, 256, SMEM_BYTES>>>(z, cb, out_zq, out_idx);
    pair_kernel<<<256, 256>>>(z, cb, out_zq, out_idx);
    full_kernel<<<512, 256>>>(z, cb, out_zq, out_idx);
}

// round 5
// speedup vs baseline: 1.9693x; 1.1002x over previous
#include <cuda_runtime.h>
#include <cuda_bf16.h>
#include <cstdint>

#define NTOK   131072
#define DIMS   256
#define NCODE  1024
#define TOKB   128
#define TPB    512
#define NCH    64                 // codes per B chunk
#define NCHUNK (NCODE / NCH)      // 16
#define MARGIN 5e-4f

// smem layout (bytes)
#define SA    0                   // A: 128 rows x 512 bf16 (hi||lo), stride 1024B, swizzled
#define SB    131072              // B: 2 x (64 rows x 256 bf16, stride 512B, swizzled)
#define SBSZ  32768
#define SESQ  196608              // 1024 f32
#define SR1V  200704
#define SR1I  202752
#define SR2V  204800
#define SR2I  206848
#define SR3V  208896
#define SIDX  210944
#define SMEM_BYTES 211456

typedef unsigned long long ull;
typedef unsigned int u32;

__device__ float g_esq[NCODE];
__device__ int   g_npair, g_nfull;
__device__ ull   g_pair[NTOK];
__device__ u32   g_full[NTOK];
__device__ __align__(16) __nv_bfloat16 g_Bh[(size_t)NCODE * DIMS];

__device__ __forceinline__ u32 s2u(const void* p) {
    u32 a; asm("{ .reg .u64 t; cvta.to.shared.u64 t, %1; cvt.u32.u64 %0, t; }" : "=r"(a) : "l"(p)); return a;
}
__device__ __forceinline__ void cpa16(u32 dst, const void* src) {
    asm volatile("cp.async.cg.shared.global [%0], [%1], 16;" :: "r"(dst), "l"(src));
}
#define CPA_COMMIT() asm volatile("cp.async.commit_group;" ::: "memory")
#define CPA_WAIT1()  asm volatile("cp.async.wait_group 1;"  ::: "memory")
#define CPA_WAIT0()  asm volatile("cp.async.wait_group 0;"  ::: "memory")

__device__ __forceinline__ void ldsm4(u32* r, u32 addr) {
    asm volatile("ldmatrix.sync.aligned.m8n8.x4.shared.b16 {%0,%1,%2,%3}, [%4];"
                 : "=r"(r[0]), "=r"(r[1]), "=r"(r[2]), "=r"(r[3]) : "r"(addr));
}
__device__ __forceinline__ void mma16816(float* c, const u32* a, const u32* b) {
    asm volatile("mma.sync.aligned.m16n8k16.row.col.f32.bf16.bf16.f32 "
                 "{%0,%1,%2,%3}, {%4,%5,%6,%7}, {%8,%9}, {%0,%1,%2,%3};"
                 : "+f"(c[0]), "+f"(c[1]), "+f"(c[2]), "+f"(c[3])
                 : "r"(a[0]), "r"(a[1]), "r"(a[2]), "r"(a[3]), "r"(b[0]), "r"(b[1]));
}
__device__ __forceinline__ u32 packbf(float lo, float hi) {   // low 16 <- lo
    u32 r; asm("cvt.rn.bf16x2.f32 %0, %1, %2;" : "=r"(r) : "f"(hi), "f"(lo)); return r;
}
__device__ __forceinline__ u32 ordf(float f) {
    u32 u = __float_as_uint(f);
    return (u & 0x80000000u) ? ~u : (u | 0x80000000u);
}
// merge sorted top-3 with another sorted top-3
__device__ __forceinline__ void merge3(float &v1, u32 &i1, float &v2, u32 &i2, float &v3,
                                       float o1, u32 oi1, float o2, u32 oi2, float o3) {
    if (o1 < v1) {
        if (v1 <= o2) { v3 = fminf(v2, o2); v2 = v1; i2 = i1; }
        else          { v3 = fminf(v1, o3); v2 = o2; i2 = oi2; }
        v1 = o1; i1 = oi1;
    } else {
        if (o1 < v2) { v3 = fminf(v2, o2); v2 = o1; i2 = oi1; }
        else         { v3 = fminf(v3, o1); }
    }
}

// ---------------- prep ----------------
__global__ void esq_kernel(const float* __restrict__ cb) {
    if (blockIdx.x == 0 && threadIdx.x == 0) { g_npair = 0; g_nfull = 0; }
    int k = blockIdx.x * blockDim.x + threadIdx.x;
    if (k >= NCODE) return;
    const float4* r = (const float4*)(cb + (size_t)k * DIMS);
    float s = 0.f;
#pragma unroll 8
    for (int i = 0; i < DIMS / 4; i++) {
        float4 v = r[i];
        s = fmaf(v.x, v.x, s); s = fmaf(v.y, v.y, s);
        s = fmaf(v.z, v.z, s); s = fmaf(v.w, v.w, s);
    }
    g_esq[k] = s;
}
__global__ void bprep_kernel(const float* __restrict__ cb) {
    int i = blockIdx.x * blockDim.x + threadIdx.x;
    g_Bh[i] = __float2bfloat16(cb[i]);
}

// ---------------- main: HMMA GEMM + top-3 argmin ----------------
__global__ __launch_bounds__(TPB, 1) void vq_kernel(
    const float* __restrict__ z, const float* __restrict__ cb,
    float* __restrict__ out_zq, float* __restrict__ out_idx)
{
    extern __shared__ __align__(16) unsigned char smem[];
    const u32 smb = s2u(smem);
    float* esq_s = (float*)(smem + SESQ);
    float* r1v = (float*)(smem + SR1V); u32* r1i = (u32*)(smem + SR1I);
    float* r2v = (float*)(smem + SR2V); u32* r2i = (u32*)(smem + SR2I);
    float* r3v = (float*)(smem + SR3V); u32* idx_s = (u32*)(smem + SIDX);

    const int tid = threadIdx.x, lane = tid & 31, wid = tid >> 5;
    const int wm = wid & 3, wn = wid >> 2;      // 4 M-groups x 4 N-groups
    const size_t tokBase = (size_t)blockIdx.x * TOKB;

    // kick B chunk 0 (64 codes x 256 bf16 = 2048 x 16B)
#pragma unroll
    for (int i = 0; i < 4; i++) {
        int flat = tid + i * TPB, row = flat >> 5, g = flat & 31;
        u32 dst = smb + SB + (u32)row * 512 + (u32)((g ^ (row & 7)) << 4);
        cpa16(dst, g_Bh + ((size_t)row * DIMS + g * 8));
    }
    CPA_COMMIT();

    // A: convert z -> bf16 hi/lo into smem (swizzled), while B0 is in flight
#pragma unroll
    for (int i = 0; i < 8; i++) {
        int flat = tid + i * TPB, row = flat >> 5, g = flat & 31;
        const float4* zp = (const float4*)(z + (tokBase + row) * DIMS + g * 8);
        float4 a = zp[0], b = zp[1];
        float hax = __bfloat162float(__float2bfloat16(a.x)), hay = __bfloat162float(__float2bfloat16(a.y));
        float haz = __bfloat162float(__float2bfloat16(a.z)), haw = __bfloat162float(__float2bfloat16(a.w));
        float hbx = __bfloat162float(__float2bfloat16(b.x)), hby = __bfloat162float(__float2bfloat16(b.y));
        float hbz = __bfloat162float(__float2bfloat16(b.z)), hbw = __bfloat162float(__float2bfloat16(b.w));
        u32 h0 = packbf(a.x, a.y), h1 = packbf(a.z, a.w), h2 = packbf(b.x, b.y), h3 = packbf(b.z, b.w);
        u32 l0 = packbf(a.x - hax, a.y - hay), l1 = packbf(a.z - haz, a.w - haw);
        u32 l2 = packbf(b.x - hbx, b.y - hby), l3 = packbf(b.z - hbz, b.w - hbw);
        u32 ah = smb + SA + (u32)row * 1024 + (u32)((g ^ (row & 7)) << 4);
        asm volatile("st.shared.v4.b32 [%0], {%1,%2,%3,%4};" :: "r"(ah), "r"(h0), "r"(h1), "r"(h2), "r"(h3));
        asm volatile("st.shared.v4.b32 [%0], {%1,%2,%3,%4};" :: "r"(ah + 512), "r"(l0), "r"(l1), "r"(l2), "r"(l3));
    }
#pragma unroll
    for (int i = 0; i < 2; i++) esq_s[tid + i * TPB] = g_esq[tid + i * TPB];

    // per-warp ldmatrix bases (fragment mapping verified in R4)
    const int t8 = lane >> 3;
    u32 aBase[2]; int aSw[2];
#pragma unroll
    for (int mt = 0; mt < 2; mt++) {
        int ar = wm * 32 + mt * 16 + (t8 & 1) * 8 + (lane & 7);
        aSw[mt] = ar & 7; aBase[mt] = smb + SA + (u32)ar * 1024;
    }
    const int akt = (lane >> 4) & 1;
    const int br = wn * 16 + (t8 >> 1) * 8 + (lane & 7);
    const int bSw = br & 7, bkt = t8 & 1;
    const u32 bRowOff = (u32)br * 512;

    // top-3 per row-slot (4 slots: mt*2 + acc-half)
    float b1v[4], b2v[4], b3v[4]; u32 b1i[4], b2i[4];
#pragma unroll
    for (int s = 0; s < 4; s++) { b1v[s] = b2v[s] = b3v[s] = 3.4e38f; b1i[s] = b2i[s] = 0; }

    for (int ch = 0; ch < NCHUNK; ch++) {
        if (ch < NCHUNK - 1) {
            const int nc = ch + 1;
#pragma unroll
            for (int i = 0; i < 4; i++) {
                int flat = tid + i * TPB, row = flat >> 5, g = flat & 31;
                u32 dst = smb + SB + (u32)((nc & 1) ? SBSZ : 0) + (u32)row * 512 + (u32)((g ^ (row & 7)) << 4);
                cpa16(dst, g_Bh + ((size_t)(nc * NCH + row) * DIMS + g * 8));
            }
            CPA_COMMIT();
            CPA_WAIT1();
        } else {
            CPA_WAIT0();
        }
        __syncthreads();

        const u32 bb = smb + SB + (u32)((ch & 1) ? SBSZ : 0) + bRowOff;
        float acc[2][2][4];
#pragma unroll
        for (int mt = 0; mt < 2; mt++)
#pragma unroll
            for (int nt = 0; nt < 2; nt++)
#pragma unroll
                for (int i = 0; i < 4; i++) acc[mt][nt][i] = 0.f;

        // software-pipelined fragments: load ks+1 while issuing mma(ks)
        u32 bF[2][4], aFh[2][2][4], aFl[2][2][4];
        ldsm4(bF[0], bb + (u32)(((0 * 2 + bkt) ^ bSw) << 4));
#pragma unroll
        for (int mt = 0; mt < 2; mt++) {
            ldsm4(aFh[0][mt], aBase[mt] + (u32)(((0 * 2 + akt) ^ aSw[mt]) << 4));
            ldsm4(aFl[0][mt], aBase[mt] + (u32)(((32 + 0 * 2 + akt) ^ aSw[mt]) << 4));
        }
#pragma unroll
        for (int ks = 0; ks < 16; ks++) {
            const int cur = ks & 1, nxt = cur ^ 1;
            if (ks < 15) {
                const int kn = ks + 1;
                ldsm4(bF[nxt], bb + (u32)(((kn * 2 + bkt) ^ bSw) << 4));
#pragma unroll
                for (int mt = 0; mt < 2; mt++) {
                    ldsm4(aFh[nxt][mt], aBase[mt] + (u32)(((kn * 2 + akt) ^ aSw[mt]) << 4));
                    ldsm4(aFl[nxt][mt], aBase[mt] + (u32)(((32 + kn * 2 + akt) ^ aSw[mt]) << 4));
                }
            }
#pragma unroll
            for (int mt = 0; mt < 2; mt++) {
                mma16816(acc[mt][0], aFh[cur][mt], bF[cur]);
                mma16816(acc[mt][1], aFh[cur][mt], bF[cur] + 2);
                mma16816(acc[mt][0], aFl[cur][mt], bF[cur]);
                mma16816(acc[mt][1], aFl[cur][mt], bF[cur] + 2);
            }
        }

        // epilogue: m = esq - 2*dot, top-3 update
#pragma unroll
        for (int mt = 0; mt < 2; mt++)
#pragma unroll
            for (int nt = 0; nt < 2; nt++)
#pragma unroll
                for (int i = 0; i < 4; i++) {
                    int c = ch * NCH + wn * 16 + nt * 8 + 2 * (lane & 3) + (i & 1);
                    float m = fmaf(-2.f, acc[mt][nt][i], esq_s[c]);
                    int s = mt * 2 + (i >> 1);
                    if (m < b1v[s]) { b3v[s] = b2v[s]; b2v[s] = b1v[s]; b2i[s] = b1i[s]; b1v[s] = m; b1i[s] = (u32)c; }
                    else if (m < b2v[s]) { b3v[s] = b2v[s]; b2v[s] = m; b2i[s] = (u32)c; }
                    else if (m < b3v[s]) b3v[s] = m;
                }
        __syncthreads();
    }

    // quad-lane merge (lanes sharing lane>>2 hold the same token row)
#pragma unroll
    for (int s = 0; s < 4; s++) {
#pragma unroll
        for (int x = 1; x <= 2; x <<= 1) {
            float o1 = __shfl_xor_sync(~0u, b1v[s], x); u32 oi1 = __shfl_xor_sync(~0u, b1i[s], x);
            float o2 = __shfl_xor_sync(~0u, b2v[s], x); u32 oi2 = __shfl_xor_sync(~0u, b2i[s], x);
            float o3 = __shfl_xor_sync(~0u, b3v[s], x);
            merge3(b1v[s], b1i[s], b2v[s], b2i[s], b3v[s], o1, oi1, o2, oi2, o3);
        }
    }
    if ((lane & 3) == 0) {
#pragma unroll
        for (int s = 0; s < 4; s++) {
            int grow = wm * 32 + (s >> 1) * 16 + (s & 1) * 8 + (lane >> 2);
            r1v[wn * 128 + grow] = b1v[s]; r1i[wn * 128 + grow] = b1i[s];
            r2v[wn * 128 + grow] = b2v[s]; r2i[wn * 128 + grow] = b2i[s];
            r3v[wn * 128 + grow] = b3v[s];
        }
    }
    __syncthreads();

    if (tid < 128) {
        float v1 = r1v[tid]; u32 i1 = r1i[tid]; float v2 = r2v[tid]; u32 i2 = r2i[tid]; float v3 = r3v[tid];
#pragma unroll
        for (int w = 1; w < 4; w++)
            merge3(v1, i1, v2, i2, v3, r1v[w * 128 + tid], r1i[w * 128 + tid],
                   r2v[w * 128 + tid], r2i[w * 128 + tid], r3v[w * 128 + tid]);
        const size_t tok = tokBase + tid;
        idx_s[tid] = i1;
        if (out_idx) out_idx[tok] = (float)i1;
        if (v2 - v1 < MARGIN) {
            if (v3 - v1 >= MARGIN) {
                int p = atomicAdd(&g_npair, 1);
                g_pair[p] = (ull)tok | ((ull)i1 << 20) | ((ull)i2 << 32);
            } else {
                int p = atomicAdd(&g_nfull, 1);
                g_full[p] = (u32)tok;
            }
        }
    }
    __syncthreads();

    if (out_zq) {
#pragma unroll
        for (int i = 0; i < 16; i++) {
            int flat = tid + i * TPB, t = flat >> 6, v = flat & 63;
            ((float4*)(out_zq + (tokBase + t) * DIMS))[v] =
                ((const float4*)(cb + (size_t)idx_s[t] * DIMS))[v];
        }
    }
}

// ---------------- exact pair rescore (2 candidates) ----------------
__global__ __launch_bounds__(256) void pair_kernel(
    const float* __restrict__ z, const float* __restrict__ cb,
    float* __restrict__ out_zq, float* __restrict__ out_idx)
{
    const int lane = threadIdx.x & 31;
    const int gw = (blockIdx.x * blockDim.x + threadIdx.x) >> 5;
    const int nw = (gridDim.x * blockDim.x) >> 5;
    const int n = g_npair;
    for (int i = gw; i < n; i += nw) {
        ull p = g_pair[i];
        u32 tok = (u32)(p & 0xFFFFFu), c1 = (u32)((p >> 20) & 0x3FFu), c2 = (u32)((p >> 32) & 0x3FFu);
        const float4* zp = (const float4*)(z + (size_t)tok * DIMS + lane * 8);
        const float4* e1 = (const float4*)(cb + (size_t)c1 * DIMS + lane * 8);
        const float4* e2 = (const float4*)(cb + (size_t)c2 * DIMS + lane * 8);
        float4 za = zp[0], zb = zp[1], a1 = e1[0], b1 = e1[1], a2 = e2[0], b2 = e2[1];
        float zsq = za.x * za.x, d1 = za.x * a1.x, d2 = za.x * a2.x;
        zsq = fmaf(za.y, za.y, zsq); d1 = fmaf(za.y, a1.y, d1); d2 = fmaf(za.y, a2.y, d2);
        zsq = fmaf(za.z, za.z, zsq); d1 = fmaf(za.z, a1.z, d1); d2 = fmaf(za.z, a2.z, d2);
        zsq = fmaf(za.w, za.w, zsq); d1 = fmaf(za.w, a1.w, d1); d2 = fmaf(za.w, a2.w, d2);
        zsq = fmaf(zb.x, zb.x, zsq); d1 = fmaf(zb.x, b1.x, d1); d2 = fmaf(zb.x, b2.x, d2);
        zsq = fmaf(zb.y, zb.y, zsq); d1 = fmaf(zb.y, b1.y, d1); d2 = fmaf(zb.y, b2.y, d2);
        zsq = fmaf(zb.z, zb.z, zsq); d1 = fmaf(zb.z, b1.z, d1); d2 = fmaf(zb.z, b2.z, d2);
        zsq = fmaf(zb.w, zb.w, zsq); d1 = fmaf(zb.w, b1.w, d1); d2 = fmaf(zb.w, b2.w, d2);
#pragma unroll
        for (int o = 16; o > 0; o >>= 1) {
            zsq += __shfl_xor_sync(~0u, zsq, o);
            d1 += __shfl_xor_sync(~0u, d1, o);
            d2 += __shfl_xor_sync(~0u, d2, o);
        }
        u32 widx;
        {
            float dd1 = __fmaf_rn(-2.f, d1, __fadd_rn(zsq, g_esq[c1]));
            float dd2 = __fmaf_rn(-2.f, d2, __fadd_rn(zsq, g_esq[c2]));
            ull k1 = ((ull)ordf(dd1) << 32) | c1, k2 = ((ull)ordf(dd2) << 32) | c2;
            widx = (u32)((k1 < k2 ? k1 : k2) & 0xffffffffu);
        }
        if (out_idx && lane == 0) out_idx[tok] = (float)widx;
        if (out_zq) {
            const float4* src = (const float4*)(cb + (size_t)widx * DIMS);
            float4* dst = (float4*)(out_zq + (size_t)tok * DIMS);
            dst[lane] = src[lane];
            dst[lane + 32] = src[lane + 32];
        }
    }
}

// ---------------- exact full rescore (rare multi-candidate tokens) ----------------
__global__ __launch_bounds__(256) void full_kernel(
    const float* __restrict__ z, const float* __restrict__ cb,
    float* __restrict__ out_zq, float* __restrict__ out_idx)
{
    __shared__ float zrow[DIMS];
    __shared__ float zsq_sh;
    __shared__ ull wb[8];
    __shared__ u32 ridx;
    const int t = threadIdx.x, lane = t & 31, w = t >> 5;
    const int n = g_nfull;
    for (int it = blockIdx.x; it < n; it += gridDim.x) {
        const size_t tok = g_full[it];
        zrow[t] = z[tok * DIMS + t];
        __syncthreads();
        if (w == 0) {
            const float* zp = &zrow[lane * 8];
            float p = zp[0] * zp[0];
#pragma unroll
            for (int i = 1; i < 8; i++) p = fmaf(zp[i], zp[i], p);
#pragma unroll
            for (int o = 16; o > 0; o >>= 1) p += __shfl_xor_sync(~0u, p, o);
            if (lane == 0) zsq_sh = p;
        }
        __syncthreads();
        const float zsq = zsq_sh;
        ull best = ~0ull;
        for (int j = 0; j < 128; j++) {
            const int c = w * 128 + j;
            const float4* e4 = (const float4*)(cb + (size_t)c * DIMS + lane * 8);
            float4 a = e4[0], b = e4[1];
            const float* zp = &zrow[lane * 8];
            float p = zp[0] * a.x;
            p = fmaf(zp[1], a.y, p); p = fmaf(zp[2], a.z, p); p = fmaf(zp[3], a.w, p);
            p = fmaf(zp[4], b.x, p); p = fmaf(zp[5], b.y, p); p = fmaf(zp[6], b.z, p);
            p = fmaf(zp[7], b.w, p);
#pragma unroll
            for (int o = 16; o > 0; o >>= 1) p += __shfl_xor_sync(~0u, p, o);
            if (lane == 0) {
                float d = __fmaf_rn(-2.f, p, __fadd_rn(zsq, g_esq[c]));
                ull pk = ((ull)ordf(d) << 32) | (u32)c;
                if (pk < best) best = pk;
            }
        }
        if (lane == 0) wb[w] = best;
        __syncthreads();
        if (t == 0) {
            ull b = wb[0];
#pragma unroll
            for (int i = 1; i < 8; i++) if (wb[i] < b) b = wb[i];
            ridx = (u32)(b & 0xffffffffu);
            if (out_idx) out_idx[tok] = (float)ridx;
        }
        __syncthreads();
        if (out_zq && t < 64)
            ((float4*)(out_zq + tok * DIMS))[t] = ((const float4*)(cb + (size_t)ridx * DIMS))[t];
        __syncthreads();
    }
}

extern "C" void kernel_launch(void* const* d_in, const int* in_sizes, int n_in,
                              void* d_out, int out_size) {
    const float* z  = (const float*)d_in[0];
    const float* cb = (const float*)d_in[1];
    float* out = (float*)d_out;
    float* out_zq = nullptr;
    float* out_idx = nullptr;
    const long long ZQ = (long long)NTOK * DIMS;
    if ((long long)out_size >= ZQ + NTOK) { out_zq = out; out_idx = out + ZQ; }
    else if ((long long)out_size >= ZQ)   { out_zq = out; }
    else                                  { out_idx = out; }

    cudaFuncSetAttribute(vq_kernel, cudaFuncAttributeMaxDynamicSharedMemorySize, SMEM_BYTES);

    esq_kernel<<<4, 256>>>(cb);
    bprep_kernel<<<NCODE, 256>>>(cb);
    vq_kernel<<<NTOK / TOKB, TPB, SMEM_BYTES>>>(z, cb, out_zq, out_idx);
    pair_kernel<<<256, 256>>>(z, cb, out_zq, out_idx);
    full_kernel<<<512, 256>>>(z, cb, out_zq, out_idx);
}

// round 6
// speedup vs baseline: 2.5414x; 1.2905x over previous
#include <cuda_runtime.h>
#include <cuda_bf16.h>
#include <cstdint>

#define NTOK   131072
#define DIMS   256
#define NCODE  1024
#define TOKB   128
#define TPB    512
#define NCH    128                // codes per B chunk
#define NCHUNK (NCODE / NCH)      // 8
#define MARGIN 6e-4f

// smem layout (bytes)
#define SA    0                   // A: 128 rows x 256 bf16 (hi only), stride 512B, swizzled
#define SB    65536               // B: 2 x (128 rows x 256 bf16, stride 512B, swizzled)
#define SBSZ  65536
#define SESQ  196608              // 1024 f32
#define SR1V  200704
#define SR1I  202752
#define SR2V  204800
#define SR2I  206848
#define SR3V  208896
#define SIDX  210944
#define SMEM_BYTES 211456

typedef unsigned long long ull;
typedef unsigned int u32;

__device__ float g_esq[NCODE];
__device__ int   g_npair, g_nfull;
__device__ ull   g_pair[NTOK];
__device__ u32   g_full[NTOK];
__device__ __align__(16) __nv_bfloat16 g_Bh[(size_t)NCODE * DIMS];

__device__ __forceinline__ u32 s2u(const void* p) {
    u32 a; asm("{ .reg .u64 t; cvta.to.shared.u64 t, %1; cvt.u32.u64 %0, t; }" : "=r"(a) : "l"(p)); return a;
}
__device__ __forceinline__ void cpa16(u32 dst, const void* src) {
    asm volatile("cp.async.cg.shared.global [%0], [%1], 16;" :: "r"(dst), "l"(src));
}
#define CPA_COMMIT() asm volatile("cp.async.commit_group;" ::: "memory")
#define CPA_WAIT1()  asm volatile("cp.async.wait_group 1;"  ::: "memory")
#define CPA_WAIT0()  asm volatile("cp.async.wait_group 0;"  ::: "memory")

__device__ __forceinline__ void ldsm4(u32* r, u32 addr) {
    asm volatile("ldmatrix.sync.aligned.m8n8.x4.shared.b16 {%0,%1,%2,%3}, [%4];"
                 : "=r"(r[0]), "=r"(r[1]), "=r"(r[2]), "=r"(r[3]) : "r"(addr));
}
__device__ __forceinline__ void mma16816(float* c, const u32* a, const u32* b) {
    asm volatile("mma.sync.aligned.m16n8k16.row.col.f32.bf16.bf16.f32 "
                 "{%0,%1,%2,%3}, {%4,%5,%6,%7}, {%8,%9}, {%0,%1,%2,%3};"
                 : "+f"(c[0]), "+f"(c[1]), "+f"(c[2]), "+f"(c[3])
                 : "r"(a[0]), "r"(a[1]), "r"(a[2]), "r"(a[3]), "r"(b[0]), "r"(b[1]));
}
__device__ __forceinline__ u32 packbf(float lo, float hi) {   // low 16 <- lo
    u32 r; asm("cvt.rn.bf16x2.f32 %0, %1, %2;" : "=r"(r) : "f"(hi), "f"(lo)); return r;
}
__device__ __forceinline__ u32 ordf(float f) {
    u32 u = __float_as_uint(f);
    return (u & 0x80000000u) ? ~u : (u | 0x80000000u);
}
// merge sorted top-3 with another sorted top-3
__device__ __forceinline__ void merge3(float &v1, u32 &i1, float &v2, u32 &i2, float &v3,
                                       float o1, u32 oi1, float o2, u32 oi2, float o3) {
    if (o1 < v1) {
        if (v1 <= o2) { v3 = fminf(v2, o2); v2 = v1; i2 = i1; }
        else          { v3 = fminf(v1, o3); v2 = o2; i2 = oi2; }
        v1 = o1; i1 = oi1;
    } else {
        if (o1 < v2) { v3 = fminf(v2, o2); v2 = o1; i2 = oi1; }
        else         { v3 = fminf(v3, o1); }
    }
}

// ---------------- prep ----------------
__global__ void esq_kernel(const float* __restrict__ cb) {
    if (blockIdx.x == 0 && threadIdx.x == 0) { g_npair = 0; g_nfull = 0; }
    int k = blockIdx.x * blockDim.x + threadIdx.x;
    if (k >= NCODE) return;
    const float4* r = (const float4*)(cb + (size_t)k * DIMS);
    float s = 0.f;
#pragma unroll 8
    for (int i = 0; i < DIMS / 4; i++) {
        float4 v = r[i];
        s = fmaf(v.x, v.x, s); s = fmaf(v.y, v.y, s);
        s = fmaf(v.z, v.z, s); s = fmaf(v.w, v.w, s);
    }
    g_esq[k] = s;
}
__global__ void bprep_kernel(const float* __restrict__ cb) {
    int i = blockIdx.x * blockDim.x + threadIdx.x;
    g_Bh[i] = __float2bfloat16(cb[i]);
}

// ---------------- main: HMMA GEMM (1-pass bf16) + top-3 argmin ----------------
__global__ __launch_bounds__(TPB, 1) void vq_kernel(
    const float* __restrict__ z, const float* __restrict__ cb,
    float* __restrict__ out_zq, float* __restrict__ out_idx)
{
    extern __shared__ __align__(16) unsigned char smem[];
    const u32 smb = s2u(smem);
    float* esq_s = (float*)(smem + SESQ);
    float* r1v = (float*)(smem + SR1V); u32* r1i = (u32*)(smem + SR1I);
    float* r2v = (float*)(smem + SR2V); u32* r2i = (u32*)(smem + SR2I);
    float* r3v = (float*)(smem + SR3V); u32* idx_s = (u32*)(smem + SIDX);

    const int tid = threadIdx.x, lane = tid & 31, wid = tid >> 5;
    const int wm = wid & 3, wn = wid >> 2;      // 4 M-groups x 4 N-groups (tile 32x32)
    const size_t tokBase = (size_t)blockIdx.x * TOKB;

    // kick B chunk 0 (128 codes x 256 bf16 = 4096 x 16B)
#pragma unroll
    for (int i = 0; i < 8; i++) {
        int flat = tid + i * TPB, row = flat >> 5, g = flat & 31;
        u32 dst = smb + SB + (u32)row * 512 + (u32)((g ^ (row & 7)) << 4);
        cpa16(dst, g_Bh + ((size_t)row * DIMS + g * 8));
    }
    CPA_COMMIT();

    // A: convert z -> bf16 (hi only) into smem (swizzled), while B0 is in flight
#pragma unroll
    for (int i = 0; i < 8; i++) {
        int flat = tid + i * TPB, row = flat >> 5, g = flat & 31;
        const float4* zp = (const float4*)(z + (tokBase + row) * DIMS + g * 8);
        float4 a = zp[0], b = zp[1];
        u32 h0 = packbf(a.x, a.y), h1 = packbf(a.z, a.w), h2 = packbf(b.x, b.y), h3 = packbf(b.z, b.w);
        u32 ah = smb + SA + (u32)row * 512 + (u32)((g ^ (row & 7)) << 4);
        asm volatile("st.shared.v4.b32 [%0], {%1,%2,%3,%4};" :: "r"(ah), "r"(h0), "r"(h1), "r"(h2), "r"(h3));
    }
#pragma unroll
    for (int i = 0; i < 2; i++) esq_s[tid + i * TPB] = g_esq[tid + i * TPB];

    // per-warp ldmatrix bases (fragment mapping verified in R4/R5)
    const int t8 = lane >> 3;
    u32 aBase[2]; int aSw[2];
#pragma unroll
    for (int mt = 0; mt < 2; mt++) {
        int ar = wm * 32 + mt * 16 + (t8 & 1) * 8 + (lane & 7);
        aSw[mt] = ar & 7; aBase[mt] = smb + SA + (u32)ar * 512;
    }
    const int akt = (lane >> 4) & 1;
    u32 bRowOff[2]; int bSw[2];
#pragma unroll
    for (int bt = 0; bt < 2; bt++) {
        int br = wn * 32 + bt * 16 + (t8 >> 1) * 8 + (lane & 7);
        bSw[bt] = br & 7; bRowOff[bt] = (u32)br * 512;
    }
    const int bkt = t8 & 1;

    // top-3 per row-slot (4 slots: mt*2 + acc-row-half)
    float b1v[4], b2v[4], b3v[4]; u32 b1i[4], b2i[4];
#pragma unroll
    for (int s = 0; s < 4; s++) { b1v[s] = b2v[s] = b3v[s] = 3.4e38f; b1i[s] = b2i[s] = 0; }

    for (int ch = 0; ch < NCHUNK; ch++) {
        if (ch < NCHUNK - 1) {
            const int nc = ch + 1;
#pragma unroll
            for (int i = 0; i < 8; i++) {
                int flat = tid + i * TPB, row = flat >> 5, g = flat & 31;
                u32 dst = smb + SB + (u32)((nc & 1) ? SBSZ : 0) + (u32)row * 512 + (u32)((g ^ (row & 7)) << 4);
                cpa16(dst, g_Bh + ((size_t)(nc * NCH + row) * DIMS + g * 8));
            }
            CPA_COMMIT();
            CPA_WAIT1();
        } else {
            CPA_WAIT0();
        }
        __syncthreads();

        const u32 bb = smb + SB + (u32)((ch & 1) ? SBSZ : 0);
        float acc[2][4][4];
#pragma unroll
        for (int mt = 0; mt < 2; mt++)
#pragma unroll
            for (int nf = 0; nf < 4; nf++)
#pragma unroll
                for (int i = 0; i < 4; i++) acc[mt][nf][i] = 0.f;

        // software-pipelined fragments: load ks+1 while issuing mma(ks)
        u32 bF[2][2][4], aF[2][2][4];
#pragma unroll
        for (int bt = 0; bt < 2; bt++)
            ldsm4(bF[0][bt], bb + bRowOff[bt] + (u32)(((0 + bkt) ^ bSw[bt]) << 4));
#pragma unroll
        for (int mt = 0; mt < 2; mt++)
            ldsm4(aF[0][mt], aBase[mt] + (u32)(((0 + akt) ^ aSw[mt]) << 4));

#pragma unroll
        for (int ks = 0; ks < 16; ks++) {
            const int cur = ks & 1, nxt = cur ^ 1;
            if (ks < 15) {
                const int k2 = (ks + 1) * 2;
#pragma unroll
                for (int bt = 0; bt < 2; bt++)
                    ldsm4(bF[nxt][bt], bb + bRowOff[bt] + (u32)(((k2 + bkt) ^ bSw[bt]) << 4));
#pragma unroll
                for (int mt = 0; mt < 2; mt++)
                    ldsm4(aF[nxt][mt], aBase[mt] + (u32)(((k2 + akt) ^ aSw[mt]) << 4));
            }
#pragma unroll
            for (int mt = 0; mt < 2; mt++) {
                mma16816(acc[mt][0], aF[cur][mt], bF[cur][0]);
                mma16816(acc[mt][1], aF[cur][mt], bF[cur][0] + 2);
                mma16816(acc[mt][2], aF[cur][mt], bF[cur][1]);
                mma16816(acc[mt][3], aF[cur][mt], bF[cur][1] + 2);
            }
        }

        // epilogue: m = esq - 2*dot, top-3 update
#pragma unroll
        for (int mt = 0; mt < 2; mt++)
#pragma unroll
            for (int nf = 0; nf < 4; nf++)
#pragma unroll
                for (int i = 0; i < 4; i++) {
                    int c = ch * NCH + wn * 32 + nf * 8 + 2 * (lane & 3) + (i & 1);
                    float m = fmaf(-2.f, acc[mt][nf][i], esq_s[c]);
                    int s = mt * 2 + (i >> 1);
                    if (m < b1v[s]) { b3v[s] = b2v[s]; b2v[s] = b1v[s]; b2i[s] = b1i[s]; b1v[s] = m; b1i[s] = (u32)c; }
                    else if (m < b2v[s]) { b3v[s] = b2v[s]; b2v[s] = m; b2i[s] = (u32)c; }
                    else if (m < b3v[s]) b3v[s] = m;
                }
        __syncthreads();
    }

    // quad-lane merge (lanes sharing lane>>2 hold the same token row)
#pragma unroll
    for (int s = 0; s < 4; s++) {
#pragma unroll
        for (int x = 1; x <= 2; x <<= 1) {
            float o1 = __shfl_xor_sync(~0u, b1v[s], x); u32 oi1 = __shfl_xor_sync(~0u, b1i[s], x);
            float o2 = __shfl_xor_sync(~0u, b2v[s], x); u32 oi2 = __shfl_xor_sync(~0u, b2i[s], x);
            float o3 = __shfl_xor_sync(~0u, b3v[s], x);
            merge3(b1v[s], b1i[s], b2v[s], b2i[s], b3v[s], o1, oi1, o2, oi2, o3);
        }
    }
    if ((lane & 3) == 0) {
#pragma unroll
        for (int s = 0; s < 4; s++) {
            int grow = wm * 32 + (s >> 1) * 16 + (s & 1) * 8 + (lane >> 2);
            r1v[wn * 128 + grow] = b1v[s]; r1i[wn * 128 + grow] = b1i[s];
            r2v[wn * 128 + grow] = b2v[s]; r2i[wn * 128 + grow] = b2i[s];
            r3v[wn * 128 + grow] = b3v[s];
        }
    }
    __syncthreads();

    if (tid < 128) {
        float v1 = r1v[tid]; u32 i1 = r1i[tid]; float v2 = r2v[tid]; u32 i2 = r2i[tid]; float v3 = r3v[tid];
#pragma unroll
        for (int w = 1; w < 4; w++)
            merge3(v1, i1, v2, i2, v3, r1v[w * 128 + tid], r1i[w * 128 + tid],
                   r2v[w * 128 + tid], r2i[w * 128 + tid], r3v[w * 128 + tid]);
        const size_t tok = tokBase + tid;
        idx_s[tid] = i1;
        if (out_idx) out_idx[tok] = (float)i1;
        if (v2 - v1 < MARGIN) {
            if (v3 - v1 >= MARGIN) {
                int p = atomicAdd(&g_npair, 1);
                g_pair[p] = (ull)tok | ((ull)i1 << 20) | ((ull)i2 << 32);
            } else {
                int p = atomicAdd(&g_nfull, 1);
                g_full[p] = (u32)tok;
            }
        }
    }
    __syncthreads();

    if (out_zq) {
#pragma unroll
        for (int i = 0; i < 16; i++) {
            int flat = tid + i * TPB, t = flat >> 6, v = flat & 63;
            ((float4*)(out_zq + (tokBase + t) * DIMS))[v] =
                ((const float4*)(cb + (size_t)idx_s[t] * DIMS))[v];
        }
    }
}

// ---------------- exact pair rescore (2 candidates) ----------------
__global__ __launch_bounds__(256) void pair_kernel(
    const float* __restrict__ z, const float* __restrict__ cb,
    float* __restrict__ out_zq, float* __restrict__ out_idx)
{
    const int lane = threadIdx.x & 31;
    const int gw = (blockIdx.x * blockDim.x + threadIdx.x) >> 5;
    const int nw = (gridDim.x * blockDim.x) >> 5;
    const int n = g_npair;
    for (int i = gw; i < n; i += nw) {
        ull p = g_pair[i];
        u32 tok = (u32)(p & 0xFFFFFu), c1 = (u32)((p >> 20) & 0x3FFu), c2 = (u32)((p >> 32) & 0x3FFu);
        const float4* zp = (const float4*)(z + (size_t)tok * DIMS + lane * 8);
        const float4* e1 = (const float4*)(cb + (size_t)c1 * DIMS + lane * 8);
        const float4* e2 = (const float4*)(cb + (size_t)c2 * DIMS + lane * 8);
        float4 za = zp[0], zb = zp[1], a1 = e1[0], b1 = e1[1], a2 = e2[0], b2 = e2[1];
        float zsq = za.x * za.x, d1 = za.x * a1.x, d2 = za.x * a2.x;
        zsq = fmaf(za.y, za.y, zsq); d1 = fmaf(za.y, a1.y, d1); d2 = fmaf(za.y, a2.y, d2);
        zsq = fmaf(za.z, za.z, zsq); d1 = fmaf(za.z, a1.z, d1); d2 = fmaf(za.z, a2.z, d2);
        zsq = fmaf(za.w, za.w, zsq); d1 = fmaf(za.w, a1.w, d1); d2 = fmaf(za.w, a2.w, d2);
        zsq = fmaf(zb.x, zb.x, zsq); d1 = fmaf(zb.x, b1.x, d1); d2 = fmaf(zb.x, b2.x, d2);
        zsq = fmaf(zb.y, zb.y, zsq); d1 = fmaf(zb.y, b1.y, d1); d2 = fmaf(zb.y, b2.y, d2);
        zsq = fmaf(zb.z, zb.z, zsq); d1 = fmaf(zb.z, b1.z, d1); d2 = fmaf(zb.z, b2.z, d2);
        zsq = fmaf(zb.w, zb.w, zsq); d1 = fmaf(zb.w, b1.w, d1); d2 = fmaf(zb.w, b2.w, d2);
#pragma unroll
        for (int o = 16; o > 0; o >>= 1) {
            zsq += __shfl_xor_sync(~0u, zsq, o);
            d1 += __shfl_xor_sync(~0u, d1, o);
            d2 += __shfl_xor_sync(~0u, d2, o);
        }
        u32 widx;
        {
            float dd1 = __fmaf_rn(-2.f, d1, __fadd_rn(zsq, g_esq[c1]));
            float dd2 = __fmaf_rn(-2.f, d2, __fadd_rn(zsq, g_esq[c2]));
            ull k1 = ((ull)ordf(dd1) << 32) | c1, k2 = ((ull)ordf(dd2) << 32) | c2;
            widx = (u32)((k1 < k2 ? k1 : k2) & 0xffffffffu);
        }
        if (out_idx && lane == 0) out_idx[tok] = (float)widx;
        if (out_zq) {
            const float4* src = (const float4*)(cb + (size_t)widx * DIMS);
            float4* dst = (float4*)(out_zq + (size_t)tok * DIMS);
            dst[lane] = src[lane];
            dst[lane + 32] = src[lane + 32];
        }
    }
}

// ---------------- exact full rescore (rare multi-candidate tokens) ----------------
__global__ __launch_bounds__(256) void full_kernel(
    const float* __restrict__ z, const float* __restrict__ cb,
    float* __restrict__ out_zq, float* __restrict__ out_idx)
{
    __shared__ float zrow[DIMS];
    __shared__ float zsq_sh;
    __shared__ ull wb[8];
    __shared__ u32 ridx;
    const int t = threadIdx.x, lane = t & 31, w = t >> 5;
    const int n = g_nfull;
    for (int it = blockIdx.x; it < n; it += gridDim.x) {
        const size_t tok = g_full[it];
        zrow[t] = z[tok * DIMS + t];
        __syncthreads();
        if (w == 0) {
            const float* zp = &zrow[lane * 8];
            float p = zp[0] * zp[0];
#pragma unroll
            for (int i = 1; i < 8; i++) p = fmaf(zp[i], zp[i], p);
#pragma unroll
            for (int o = 16; o > 0; o >>= 1) p += __shfl_xor_sync(~0u, p, o);
            if (lane == 0) zsq_sh = p;
        }
        __syncthreads();
        const float zsq = zsq_sh;
        ull best = ~0ull;
        for (int j = 0; j < 128; j++) {
            const int c = w * 128 + j;
            const float4* e4 = (const float4*)(cb + (size_t)c * DIMS + lane * 8);
            float4 a = e4[0], b = e4[1];
            const float* zp = &zrow[lane * 8];
            float p = zp[0] * a.x;
            p = fmaf(zp[1], a.y, p); p = fmaf(zp[2], a.z, p); p = fmaf(zp[3], a.w, p);
            p = fmaf(zp[4], b.x, p); p = fmaf(zp[5], b.y, p); p = fmaf(zp[6], b.z, p);
            p = fmaf(zp[7], b.w, p);
#pragma unroll
            for (int o = 16; o > 0; o >>= 1) p += __shfl_xor_sync(~0u, p, o);
            if (lane == 0) {
                float d = __fmaf_rn(-2.f, p, __fadd_rn(zsq, g_esq[c]));
                ull pk = ((ull)ordf(d) << 32) | (u32)c;
                if (pk < best) best = pk;
            }
        }
        if (lane == 0) wb[w] = best;
        __syncthreads();
        if (t == 0) {
            ull b = wb[0];
#pragma unroll
            for (int i = 1; i < 8; i++) if (wb[i] < b) b = wb[i];
            ridx = (u32)(b & 0xffffffffu);
            if (out_idx) out_idx[tok] = (float)ridx;
        }
        __syncthreads();
        if (out_zq && t < 64)
            ((float4*)(out_zq + tok * DIMS))[t] = ((const float4*)(cb + (size_t)ridx * DIMS))[t];
        __syncthreads();
    }
}

extern "C" void kernel_launch(void* const* d_in, const int* in_sizes, int n_in,
                              void* d_out, int out_size) {
    const float* z  = (const float*)d_in[0];
    const float* cb = (const float*)d_in[1];
    float* out = (float*)d_out;
    float* out_zq = nullptr;
    float* out_idx = nullptr;
    const long long ZQ = (long long)NTOK * DIMS;
    if ((long long)out_size >= ZQ + NTOK) { out_zq = out; out_idx = out + ZQ; }
    else if ((long long)out_size >= ZQ)   { out_zq = out; }
    else                                  { out_idx = out; }

    cudaFuncSetAttribute(vq_kernel, cudaFuncAttributeMaxDynamicSharedMemorySize, SMEM_BYTES);

    esq_kernel<<<4, 256>>>(cb);
    bprep_kernel<<<NCODE, 256>>>(cb);
    vq_kernel<<<NTOK / TOKB, TPB, SMEM_BYTES>>>(z, cb, out_zq, out_idx);
    pair_kernel<<<256, 256>>>(z, cb, out_zq, out_idx);
    full_kernel<<<512, 256>>>(z, cb, out_zq, out_idx);
}

// round 7
// speedup vs baseline: 2.6140x; 1.0286x over previous
#include <cuda_runtime.h>
#include <cuda_bf16.h>
#include <cstdint>

#define NTOK   131072
#define DIMS   256
#define NCODE  1024
#define TOKB   64
#define TPB    256
#define NCH    64                 // codes per B chunk
#define NCHUNK (NCODE / NCH)      // 16
#define MARGIN 6e-4f

// smem layout (bytes)
#define SA    0                   // A: 64 rows x 256 bf16, stride 512B, swizzled = 32KB
#define SB    32768               // B: 2 x (64 rows x 256 bf16, stride 512B, swizzled)
#define SBSZ  32768
#define SESQ  98304               // 1024 f32
#define SR1V  102400              // 4 N-groups x 64 rows
#define SR1I  103424
#define SR2V  104448
#define SR2I  105472
#define SR3V  106496
#define SIDX  107520
#define SMEM_BYTES 108544

typedef unsigned long long ull;
typedef unsigned int u32;

__device__ float g_esq[NCODE];
__device__ int   g_npair, g_nfull;
__device__ ull   g_pair[NTOK];
__device__ u32   g_full[NTOK];
__device__ __align__(16) __nv_bfloat16 g_Bh[(size_t)NCODE * DIMS];

__device__ __forceinline__ u32 s2u(const void* p) {
    u32 a; asm("{ .reg .u64 t; cvta.to.shared.u64 t, %1; cvt.u32.u64 %0, t; }" : "=r"(a) : "l"(p)); return a;
}
__device__ __forceinline__ void cpa16(u32 dst, const void* src) {
    asm volatile("cp.async.cg.shared.global [%0], [%1], 16;" :: "r"(dst), "l"(src));
}
#define CPA_COMMIT() asm volatile("cp.async.commit_group;" ::: "memory")
#define CPA_WAIT1()  asm volatile("cp.async.wait_group 1;"  ::: "memory")
#define CPA_WAIT0()  asm volatile("cp.async.wait_group 0;"  ::: "memory")

__device__ __forceinline__ void ldsm4(u32* r, u32 addr) {
    asm volatile("ldmatrix.sync.aligned.m8n8.x4.shared.b16 {%0,%1,%2,%3}, [%4];"
                 : "=r"(r[0]), "=r"(r[1]), "=r"(r[2]), "=r"(r[3]) : "r"(addr));
}
__device__ __forceinline__ void mma16816(float* c, const u32* a, const u32* b) {
    asm volatile("mma.sync.aligned.m16n8k16.row.col.f32.bf16.bf16.f32 "
                 "{%0,%1,%2,%3}, {%4,%5,%6,%7}, {%8,%9}, {%0,%1,%2,%3};"
                 : "+f"(c[0]), "+f"(c[1]), "+f"(c[2]), "+f"(c[3])
                 : "r"(a[0]), "r"(a[1]), "r"(a[2]), "r"(a[3]), "r"(b[0]), "r"(b[1]));
}
__device__ __forceinline__ u32 packbf(float lo, float hi) {   // low 16 <- lo
    u32 r; asm("cvt.rn.bf16x2.f32 %0, %1, %2;" : "=r"(r) : "f"(hi), "f"(lo)); return r;
}
__device__ __forceinline__ u32 ordf(float f) {
    u32 u = __float_as_uint(f);
    return (u & 0x80000000u) ? ~u : (u | 0x80000000u);
}
// merge sorted top-3 with another sorted top-3
__device__ __forceinline__ void merge3(float &v1, u32 &i1, float &v2, u32 &i2, float &v3,
                                       float o1, u32 oi1, float o2, u32 oi2, float o3) {
    if (o1 < v1) {
        if (v1 <= o2) { v3 = fminf(v2, o2); v2 = v1; i2 = i1; }
        else          { v3 = fminf(v1, o3); v2 = o2; i2 = oi2; }
        v1 = o1; i1 = oi1;
    } else {
        if (o1 < v2) { v3 = fminf(v2, o2); v2 = o1; i2 = oi1; }
        else         { v3 = fminf(v3, o1); }
    }
}

// ---------------- merged prep: bf16 codebook + esq ----------------
__global__ __launch_bounds__(256) void prep_kernel(const float* __restrict__ cb) {
    __shared__ float ws[8];
    const int code = blockIdx.x, d = threadIdx.x;
    if (code == 0 && d == 0) { g_npair = 0; g_nfull = 0; }
    float e = cb[(size_t)code * DIMS + d];
    g_Bh[(size_t)code * DIMS + d] = __float2bfloat16(e);
    float s = e * e;
#pragma unroll
    for (int o = 16; o > 0; o >>= 1) s += __shfl_xor_sync(~0u, s, o);
    if ((d & 31) == 0) ws[d >> 5] = s;
    __syncthreads();
    if (d == 0) {
        float t = 0.f;
#pragma unroll
        for (int i = 0; i < 8; i++) t += ws[i];
        g_esq[code] = t;
    }
}

// ---------------- main: HMMA GEMM (1-pass bf16) + top-3 argmin, occ 2 ----------------
__global__ __launch_bounds__(TPB, 2) void vq_kernel(
    const float* __restrict__ z, const float* __restrict__ cb,
    float* __restrict__ out_zq, float* __restrict__ out_idx)
{
    extern __shared__ __align__(16) unsigned char smem[];
    const u32 smb = s2u(smem);
    float* esq_s = (float*)(smem + SESQ);
    float* r1v = (float*)(smem + SR1V); u32* r1i = (u32*)(smem + SR1I);
    float* r2v = (float*)(smem + SR2V); u32* r2i = (u32*)(smem + SR2I);
    float* r3v = (float*)(smem + SR3V); u32* idx_s = (u32*)(smem + SIDX);

    const int tid = threadIdx.x, lane = tid & 31, wid = tid >> 5;
    const int wm = wid & 1, wn = wid >> 1;      // 2 M-groups x 4 N-groups (tile 32x16)
    const size_t tokBase = (size_t)blockIdx.x * TOKB;

    // kick B chunk 0 (64 codes x 256 bf16 = 2048 x 16B)
#pragma unroll
    for (int i = 0; i < 8; i++) {
        int flat = tid + i * TPB, row = flat >> 5, g = flat & 31;
        u32 dst = smb + SB + (u32)row * 512 + (u32)((g ^ (row & 7)) << 4);
        cpa16(dst, g_Bh + ((size_t)row * DIMS + g * 8));
    }
    CPA_COMMIT();

    // A: convert z -> bf16 into smem (swizzled), while B0 is in flight
#pragma unroll
    for (int i = 0; i < 8; i++) {
        int flat = tid + i * TPB, row = flat >> 5, g = flat & 31;
        const float4* zp = (const float4*)(z + (tokBase + row) * DIMS + g * 8);
        float4 a = zp[0], b = zp[1];
        u32 h0 = packbf(a.x, a.y), h1 = packbf(a.z, a.w), h2 = packbf(b.x, b.y), h3 = packbf(b.z, b.w);
        u32 ah = smb + SA + (u32)row * 512 + (u32)((g ^ (row & 7)) << 4);
        asm volatile("st.shared.v4.b32 [%0], {%1,%2,%3,%4};" :: "r"(ah), "r"(h0), "r"(h1), "r"(h2), "r"(h3));
    }
#pragma unroll
    for (int i = 0; i < 4; i++) esq_s[tid + i * TPB] = g_esq[tid + i * TPB];

    // per-warp ldmatrix bases (fragment maps verified R4-R6)
    const int t8 = lane >> 3;
    u32 aBase[2]; int aSw[2];
#pragma unroll
    for (int mt = 0; mt < 2; mt++) {
        int ar = wm * 32 + mt * 16 + (t8 & 1) * 8 + (lane & 7);
        aSw[mt] = ar & 7; aBase[mt] = smb + SA + (u32)ar * 512;
    }
    const int akt = (lane >> 4) & 1;
    const int br = wn * 16 + (t8 >> 1) * 8 + (lane & 7);
    const int bSw = br & 7, bkt = t8 & 1;
    const u32 bRowOff = (u32)br * 512;

    // top-3 per row-slot (4 slots: mt*2 + acc-row-half)
    float b1v[4], b2v[4], b3v[4]; u32 b1i[4], b2i[4];
#pragma unroll
    for (int s = 0; s < 4; s++) { b1v[s] = b2v[s] = b3v[s] = 3.4e38f; b1i[s] = b2i[s] = 0; }

    for (int ch = 0; ch < NCHUNK; ch++) {
        if (ch < NCHUNK - 1) {
            const int nc = ch + 1;
#pragma unroll
            for (int i = 0; i < 8; i++) {
                int flat = tid + i * TPB, row = flat >> 5, g = flat & 31;
                u32 dst = smb + SB + (u32)((nc & 1) ? SBSZ : 0) + (u32)row * 512 + (u32)((g ^ (row & 7)) << 4);
                cpa16(dst, g_Bh + ((size_t)(nc * NCH + row) * DIMS + g * 8));
            }
            CPA_COMMIT();
            CPA_WAIT1();
        } else {
            CPA_WAIT0();
        }
        __syncthreads();

        const u32 bb = smb + SB + (u32)((ch & 1) ? SBSZ : 0) + bRowOff;
        float acc[2][2][4];
#pragma unroll
        for (int mt = 0; mt < 2; mt++)
#pragma unroll
            for (int nt = 0; nt < 2; nt++)
#pragma unroll
                for (int i = 0; i < 4; i++) acc[mt][nt][i] = 0.f;

        // software-pipelined fragments
        u32 bF[2][4], aF[2][2][4];
        ldsm4(bF[0], bb + (u32)(((0 + bkt) ^ bSw) << 4));
#pragma unroll
        for (int mt = 0; mt < 2; mt++)
            ldsm4(aF[0][mt], aBase[mt] + (u32)(((0 + akt) ^ aSw[mt]) << 4));

#pragma unroll
        for (int ks = 0; ks < 16; ks++) {
            const int cur = ks & 1, nxt = cur ^ 1;
            if (ks < 15) {
                const int k2 = (ks + 1) * 2;
                ldsm4(bF[nxt], bb + (u32)(((k2 + bkt) ^ bSw) << 4));
#pragma unroll
                for (int mt = 0; mt < 2; mt++)
                    ldsm4(aF[nxt][mt], aBase[mt] + (u32)(((k2 + akt) ^ aSw[mt]) << 4));
            }
#pragma unroll
            for (int mt = 0; mt < 2; mt++) {
                mma16816(acc[mt][0], aF[cur][mt], bF[cur]);
                mma16816(acc[mt][1], aF[cur][mt], bF[cur] + 2);
            }
        }

        // epilogue: m = esq - 2*dot, top-3 update
#pragma unroll
        for (int mt = 0; mt < 2; mt++)
#pragma unroll
            for (int nt = 0; nt < 2; nt++)
#pragma unroll
                for (int i = 0; i < 4; i++) {
                    int c = ch * NCH + wn * 16 + nt * 8 + 2 * (lane & 3) + (i & 1);
                    float m = fmaf(-2.f, acc[mt][nt][i], esq_s[c]);
                    int s = mt * 2 + (i >> 1);
                    if (m < b1v[s]) { b3v[s] = b2v[s]; b2v[s] = b1v[s]; b2i[s] = b1i[s]; b1v[s] = m; b1i[s] = (u32)c; }
                    else if (m < b2v[s]) { b3v[s] = b2v[s]; b2v[s] = m; b2i[s] = (u32)c; }
                    else if (m < b3v[s]) b3v[s] = m;
                }
        __syncthreads();
    }

    // quad-lane merge (lanes sharing lane>>2 hold the same token row)
#pragma unroll
    for (int s = 0; s < 4; s++) {
#pragma unroll
        for (int x = 1; x <= 2; x <<= 1) {
            float o1 = __shfl_xor_sync(~0u, b1v[s], x); u32 oi1 = __shfl_xor_sync(~0u, b1i[s], x);
            float o2 = __shfl_xor_sync(~0u, b2v[s], x); u32 oi2 = __shfl_xor_sync(~0u, b2i[s], x);
            float o3 = __shfl_xor_sync(~0u, b3v[s], x);
            merge3(b1v[s], b1i[s], b2v[s], b2i[s], b3v[s], o1, oi1, o2, oi2, o3);
        }
    }
    if ((lane & 3) == 0) {
#pragma unroll
        for (int s = 0; s < 4; s++) {
            int grow = wm * 32 + (s >> 1) * 16 + (s & 1) * 8 + (lane >> 2);
            r1v[wn * 64 + grow] = b1v[s]; r1i[wn * 64 + grow] = b1i[s];
            r2v[wn * 64 + grow] = b2v[s]; r2i[wn * 64 + grow] = b2i[s];
            r3v[wn * 64 + grow] = b3v[s];
        }
    }
    __syncthreads();

    if (tid < 64) {
        float v1 = r1v[tid]; u32 i1 = r1i[tid]; float v2 = r2v[tid]; u32 i2 = r2i[tid]; float v3 = r3v[tid];
#pragma unroll
        for (int w = 1; w < 4; w++)
            merge3(v1, i1, v2, i2, v3, r1v[w * 64 + tid], r1i[w * 64 + tid],
                   r2v[w * 64 + tid], r2i[w * 64 + tid], r3v[w * 64 + tid]);
        const size_t tok = tokBase + tid;
        idx_s[tid] = i1;
        if (out_idx) out_idx[tok] = (float)i1;
        if (v2 - v1 < MARGIN) {
            if (v3 - v1 >= MARGIN) {
                int p = atomicAdd(&g_npair, 1);
                g_pair[p] = (ull)tok | ((ull)i1 << 20) | ((ull)i2 << 32);
            } else {
                int p = atomicAdd(&g_nfull, 1);
                g_full[p] = (u32)tok;
            }
        }
    }
    __syncthreads();

    if (out_zq) {
#pragma unroll
        for (int i = 0; i < 16; i++) {
            int flat = tid + i * TPB, t = flat >> 6, v = flat & 63;
            ((float4*)(out_zq + (tokBase + t) * DIMS))[v] =
                ((const float4*)(cb + (size_t)idx_s[t] * DIMS))[v];
        }
    }
}

// ---------------- exact pair rescore (2 candidates) ----------------
__global__ __launch_bounds__(256) void pair_kernel(
    const float* __restrict__ z, const float* __restrict__ cb,
    float* __restrict__ out_zq, float* __restrict__ out_idx)
{
    const int lane = threadIdx.x & 31;
    const int gw = (blockIdx.x * blockDim.x + threadIdx.x) >> 5;
    const int nw = (gridDim.x * blockDim.x) >> 5;
    const int n = g_npair;
    for (int i = gw; i < n; i += nw) {
        ull p = g_pair[i];
        u32 tok = (u32)(p & 0xFFFFFu), c1 = (u32)((p >> 20) & 0x3FFu), c2 = (u32)((p >> 32) & 0x3FFu);
        const float4* zp = (const float4*)(z + (size_t)tok * DIMS + lane * 8);
        const float4* e1 = (const float4*)(cb + (size_t)c1 * DIMS + lane * 8);
        const float4* e2 = (const float4*)(cb + (size_t)c2 * DIMS + lane * 8);
        float4 za = zp[0], zb = zp[1], a1 = e1[0], b1 = e1[1], a2 = e2[0], b2 = e2[1];
        float zsq = za.x * za.x, d1 = za.x * a1.x, d2 = za.x * a2.x;
        zsq = fmaf(za.y, za.y, zsq); d1 = fmaf(za.y, a1.y, d1); d2 = fmaf(za.y, a2.y, d2);
        zsq = fmaf(za.z, za.z, zsq); d1 = fmaf(za.z, a1.z, d1); d2 = fmaf(za.z, a2.z, d2);
        zsq = fmaf(za.w, za.w, zsq); d1 = fmaf(za.w, a1.w, d1); d2 = fmaf(za.w, a2.w, d2);
        zsq = fmaf(zb.x, zb.x, zsq); d1 = fmaf(zb.x, b1.x, d1); d2 = fmaf(zb.x, b2.x, d2);
        zsq = fmaf(zb.y, zb.y, zsq); d1 = fmaf(zb.y, b1.y, d1); d2 = fmaf(zb.y, b2.y, d2);
        zsq = fmaf(zb.z, zb.z, zsq); d1 = fmaf(zb.z, b1.z, d1); d2 = fmaf(zb.z, b2.z, d2);
        zsq = fmaf(zb.w, zb.w, zsq); d1 = fmaf(zb.w, b1.w, d1); d2 = fmaf(zb.w, b2.w, d2);
#pragma unroll
        for (int o = 16; o > 0; o >>= 1) {
            zsq += __shfl_xor_sync(~0u, zsq, o);
            d1 += __shfl_xor_sync(~0u, d1, o);
            d2 += __shfl_xor_sync(~0u, d2, o);
        }
        u32 widx;
        {
            float dd1 = __fmaf_rn(-2.f, d1, __fadd_rn(zsq, g_esq[c1]));
            float dd2 = __fmaf_rn(-2.f, d2, __fadd_rn(zsq, g_esq[c2]));
            ull k1 = ((ull)ordf(dd1) << 32) | c1, k2 = ((ull)ordf(dd2) << 32) | c2;
            widx = (u32)((k1 < k2 ? k1 : k2) & 0xffffffffu);
        }
        if (out_idx && lane == 0) out_idx[tok] = (float)widx;
        if (out_zq) {
            const float4* src = (const float4*)(cb + (size_t)widx * DIMS);
            float4* dst = (float4*)(out_zq + (size_t)tok * DIMS);
            dst[lane] = src[lane];
            dst[lane + 32] = src[lane + 32];
        }
    }
}

// ---------------- exact full rescore (rare multi-candidate tokens) ----------------
__global__ __launch_bounds__(256) void full_kernel(
    const float* __restrict__ z, const float* __restrict__ cb,
    float* __restrict__ out_zq, float* __restrict__ out_idx)
{
    __shared__ float zrow[DIMS];
    __shared__ float zsq_sh;
    __shared__ ull wb[8];
    __shared__ u32 ridx;
    const int t = threadIdx.x, lane = t & 31, w = t >> 5;
    const int n = g_nfull;
    for (int it = blockIdx.x; it < n; it += gridDim.x) {
        const size_t tok = g_full[it];
        zrow[t] = z[tok * DIMS + t];
        __syncthreads();
        if (w == 0) {
            const float* zp = &zrow[lane * 8];
            float p = zp[0] * zp[0];
#pragma unroll
            for (int i = 1; i < 8; i++) p = fmaf(zp[i], zp[i], p);
#pragma unroll
            for (int o = 16; o > 0; o >>= 1) p += __shfl_xor_sync(~0u, p, o);
            if (lane == 0) zsq_sh = p;
        }
        __syncthreads();
        const float zsq = zsq_sh;
        ull best = ~0ull;
        for (int j = 0; j < 128; j++) {
            const int c = w * 128 + j;
            const float4* e4 = (const float4*)(cb + (size_t)c * DIMS + lane * 8);
            float4 a = e4[0], b = e4[1];
            const float* zp = &zrow[lane * 8];
            float p = zp[0] * a.x;
            p = fmaf(zp[1], a.y, p); p = fmaf(zp[2], a.z, p); p = fmaf(zp[3], a.w, p);
            p = fmaf(zp[4], b.x, p); p = fmaf(zp[5], b.y, p); p = fmaf(zp[6], b.z, p);
            p = fmaf(zp[7], b.w, p);
#pragma unroll
            for (int o = 16; o > 0; o >>= 1) p += __shfl_xor_sync(~0u, p, o);
            if (lane == 0) {
                float d = __fmaf_rn(-2.f, p, __fadd_rn(zsq, g_esq[c]));
                ull pk = ((ull)ordf(d) << 32) | (u32)c;
                if (pk < best) best = pk;
            }
        }
        if (lane == 0) wb[w] = best;
        __syncthreads();
        if (t == 0) {
            ull b = wb[0];
#pragma unroll
            for (int i = 1; i < 8; i++) if (wb[i] < b) b = wb[i];
            ridx = (u32)(b & 0xffffffffu);
            if (out_idx) out_idx[tok] = (float)ridx;
        }
        __syncthreads();
        if (out_zq && t < 64)
            ((float4*)(out_zq + tok * DIMS))[t] = ((const float4*)(cb + (size_t)ridx * DIMS))[t];
        __syncthreads();
    }
}

extern "C" void kernel_launch(void* const* d_in, const int* in_sizes, int n_in,
                              void* d_out, int out_size) {
    const float* z  = (const float*)d_in[0];
    const float* cb = (const float*)d_in[1];
    float* out = (float*)d_out;
    float* out_zq = nullptr;
    float* out_idx = nullptr;
    const long long ZQ = (long long)NTOK * DIMS;
    if ((long long)out_size >= ZQ + NTOK) { out_zq = out; out_idx = out + ZQ; }
    else if ((long long)out_size >= ZQ)   { out_zq = out; }
    else                                  { out_idx = out; }

    cudaFuncSetAttribute(vq_kernel, cudaFuncAttributeMaxDynamicSharedMemorySize, SMEM_BYTES);

    prep_kernel<<<NCODE, 256>>>(cb);
    vq_kernel<<<NTOK / TOKB, TPB, SMEM_BYTES>>>(z, cb, out_zq, out_idx);
    pair_kernel<<<256, 256>>>(z, cb, out_zq, out_idx);
    full_kernel<<<512, 256>>>(z, cb, out_zq, out_idx);
}